// round 1
// baseline (speedup 1.0000x reference)
#include <cuda_runtime.h>
#include <math.h>

// Problem constants
// B=4, S=2048, HID=1024, H=8, KV=2, HD=128, G=4
// M = B*S = 8192 token rows.

#define M_ROWS   8192
#define S_LEN    2048
#define NB       4
#define NH       8
#define NKV      2
#define HD       128

// ---------------- scratch (static device globals; no allocation allowed) ----
__device__ float g_qkv [(size_t)M_ROWS * 2560];           // fused qg|k|v projection
__device__ float g_q   [(size_t)NB * NH  * S_LEN * HD];   // [b][h][s][d]  (normed+roped)
__device__ float g_k   [(size_t)NB * NKV * S_LEN * HD];   // [b][kv][s][d]
__device__ float g_v   [(size_t)NB * NKV * S_LEN * HD];   // [b][kv][s][d]
__device__ float g_gate[(size_t)NB * S_LEN * NH * HD];    // [b][s][h][d]
__device__ float g_ctx [(size_t)M_ROWS * 1024];           // gated attention out [b*s][h*d]

// ---------------------------------------------------------------------------
// Generic SGEMM with bias: C[m, ccol0+n] = A[m,:K] @ Bm[:K, n] + bias[n]
// A row-major (lda=K), Bm row-major (ldb=N), C row stride ldc.
// Block tile 128x128, K-step 16, 256 threads, 8x8 per-thread microtile.
// ---------------------------------------------------------------------------
__global__ __launch_bounds__(256) void sgemm_bias(
    const float* __restrict__ A, const float* __restrict__ Bm,
    const float* __restrict__ bias, float* __restrict__ C,
    int N, int K, int ldc, int ccol0)
{
    __shared__ float As[16][132];   // transposed A tile, padded vs bank conflicts
    __shared__ float Bs[16][128];

    const int t  = threadIdx.x;
    const int tx = t & 15;          // n-direction (8 cols each)
    const int ty = t >> 4;          // m-direction (8 rows each)
    const int n0 = blockIdx.x * 128;
    const int m0 = blockIdx.y * 128;

    float acc[8][8];
#pragma unroll
    for (int i = 0; i < 8; i++)
#pragma unroll
        for (int j = 0; j < 8; j++) acc[i][j] = 0.f;

    for (int k0 = 0; k0 < K; k0 += 16) {
#pragma unroll
        for (int l = 0; l < 2; l++) {
            int f  = t + l * 256;
            int r  = f >> 2, kc = f & 3;
            float4 a = *(const float4*)(A + (size_t)(m0 + r) * K + k0 + kc * 4);
            As[kc * 4 + 0][r] = a.x;
            As[kc * 4 + 1][r] = a.y;
            As[kc * 4 + 2][r] = a.z;
            As[kc * 4 + 3][r] = a.w;
            int r2 = f >> 5, c = f & 31;
            float4 b = *(const float4*)(Bm + (size_t)(k0 + r2) * N + n0 + c * 4);
            *(float4*)(&Bs[r2][c * 4]) = b;
        }
        __syncthreads();

#pragma unroll
        for (int kk = 0; kk < 16; kk++) {
            float ar[8], br[8];
            *(float4*)&ar[0] = *(const float4*)&As[kk][ty * 8];
            *(float4*)&ar[4] = *(const float4*)&As[kk][ty * 8 + 4];
            *(float4*)&br[0] = *(const float4*)&Bs[kk][tx * 8];
            *(float4*)&br[4] = *(const float4*)&Bs[kk][tx * 8 + 4];
#pragma unroll
            for (int i = 0; i < 8; i++)
#pragma unroll
                for (int j = 0; j < 8; j++)
                    acc[i][j] = fmaf(ar[i], br[j], acc[i][j]);
        }
        __syncthreads();
    }

#pragma unroll
    for (int i = 0; i < 8; i++) {
        int row = m0 + ty * 8 + i;
        float* cp = C + (size_t)row * ldc + ccol0 + n0 + tx * 8;
#pragma unroll
        for (int j = 0; j < 8; j += 4) {
            float4 o;
            o.x = acc[i][j + 0] + bias[n0 + tx * 8 + j + 0];
            o.y = acc[i][j + 1] + bias[n0 + tx * 8 + j + 1];
            o.z = acc[i][j + 2] + bias[n0 + tx * 8 + j + 2];
            o.w = acc[i][j + 3] + bias[n0 + tx * 8 + j + 3];
            *(float4*)(cp + j) = o;
        }
    }
}

// ---------------------------------------------------------------------------
// Transform: per (b,s) token row of g_qkv, apply RMSNorm + RoPE to Q and K
// heads, copy V, copy gate. 12 warps: 0-7 q heads, 8-9 k heads, 10 v, 11 gate.
// qkv row layout: [kv0: q(512)|gate(512)][kv1: q(512)|gate(512)][k(256)][v(256)]
// ---------------------------------------------------------------------------
__global__ __launch_bounds__(384) void transform_kernel(
    const float* __restrict__ qkv, const float* __restrict__ rope,
    const float* __restrict__ qw,  const float* __restrict__ kw)
{
    const int bs = blockIdx.x;
    const int b  = bs >> 11;       // / 2048
    const int s  = bs & 2047;
    const float* row = qkv + (size_t)bs * 2560;
    const float* emb = rope + (size_t)s * 256;   // [sin(128) | cos(128)]
    const int w    = threadIdx.x >> 5;
    const int lane = threadIdx.x & 31;

    if (w < 10) {
        const bool isq = (w < 8);
        int off, outbase;
        const float* nw;
        if (isq) {
            int kvh = w >> 2;
            off     = kvh * 1024 + (w & 3) * 128;
            nw      = qw;
            outbase = ((b * NH + w) * S_LEN + s) * HD;
        } else {
            int j   = w - 8;
            off     = 2048 + j * 128;
            nw      = kw;
            outbase = ((b * NKV + j) * S_LEN + s) * HD;
        }
        const int d = lane * 4;
        float4 x = *(const float4*)(row + off + d);
        float ss = x.x * x.x + x.y * x.y + x.z * x.z + x.w * x.w;
#pragma unroll
        for (int o = 16; o > 0; o >>= 1) ss += __shfl_xor_sync(0xffffffffu, ss, o);
        float rn = rsqrtf(ss * (1.0f / 128.0f) + 1e-6f);
        float4 wv = *(const float4*)(nw + d);
        x.x *= rn * wv.x; x.y *= rn * wv.y; x.z *= rn * wv.z; x.w *= rn * wv.w;
        float4 sn = *(const float4*)(emb + d);
        float4 cs = *(const float4*)(emb + 128 + d);
        float4 y;
        y.x = x.x * cs.x - x.y * sn.x;
        y.y = x.y * cs.y + x.x * sn.y;
        y.z = x.z * cs.z - x.w * sn.z;
        y.w = x.w * cs.w + x.z * sn.w;
        float* dst = (isq ? g_q : g_k) + outbase + d;
        *(float4*)dst = y;
    } else if (w == 10) {
#pragma unroll
        for (int rr = 0; rr < 2; rr++) {
            int f = lane + rr * 32;
            int j = f >> 5, c = f & 31;
            float4 v = *(const float4*)(row + 2304 + j * 128 + c * 4);
            *(float4*)(g_v + ((size_t)((b * NKV + j) * S_LEN + s)) * HD + c * 4) = v;
        }
    } else {
#pragma unroll
        for (int rr = 0; rr < 8; rr++) {
            int f  = lane + rr * 32;
            int hh = f >> 5, c = f & 31;
            int src = (hh >> 2) * 1024 + 512 + (hh & 3) * 128 + c * 4;
            float4 v = *(const float4*)(row + src);
            *(float4*)(g_gate + ((size_t)(bs * NH + hh)) * HD + c * 4) = v;
        }
    }
}

// ---------------------------------------------------------------------------
// Flash attention (non-causal, full softmax over S=2048) + sigmoid-gate fuse.
// Block: 64 queries x one (b,h). 256 threads: tx in [0,16) keys/dims groups,
// ty in [0,16) query groups. K-tile 64 per iteration, 32 iterations.
// ---------------------------------------------------------------------------
#define SMEM_ATTN_FLOATS (64 * 129 * 2 + 64 * 128 + 64 * 68)
#define SMEM_ATTN_BYTES  (SMEM_ATTN_FLOATS * 4)

__global__ __launch_bounds__(256) void attn_kernel()
{
    extern __shared__ float smem[];
    float* Qs = smem;                 // [64][129]  pre-scaled queries
    float* Ks = smem + 64 * 129;      // [64][129]
    float* Vs = Ks + 64 * 129;        // [64][128]
    float* Ps = Vs + 64 * 128;        // [64][68]

    const int t  = threadIdx.x;
    const int tx = t & 15;
    const int ty = t >> 4;
    const int b  = blockIdx.z;
    const int h  = blockIdx.y;
    const int q0 = blockIdx.x * 64;
    const int kv = h >> 2;            // GQA group G=4
    const float scale = 0.08838834764831845f;   // 1/sqrt(128)

    const float* Qg = g_q + ((size_t)((b * NH + h) * S_LEN + q0)) * HD;
    const float* Kb = g_k + ((size_t)(b * NKV + kv)) * S_LEN * HD;
    const float* Vb = g_v + ((size_t)(b * NKV + kv)) * S_LEN * HD;

#pragma unroll
    for (int l = 0; l < 8; l++) {
        int f = t + l * 256, r = f >> 5, c = f & 31;
        float4 v = *(const float4*)(Qg + r * 128 + c * 4);
        float* dst = Qs + r * 129 + c * 4;
        dst[0] = v.x * scale; dst[1] = v.y * scale;
        dst[2] = v.z * scale; dst[3] = v.w * scale;
    }

    float m_[4], l_[4], o_[4][8];
#pragma unroll
    for (int i = 0; i < 4; i++) {
        m_[i] = -1e30f; l_[i] = 0.f;
#pragma unroll
        for (int j = 0; j < 8; j++) o_[i][j] = 0.f;
    }

    for (int kt = 0; kt < 32; kt++) {
        __syncthreads();   // previous tile fully consumed (also fences Q load)
        const float* Kt = Kb + (size_t)kt * 64 * 128;
        const float* Vt = Vb + (size_t)kt * 64 * 128;
#pragma unroll
        for (int l = 0; l < 8; l++) {
            int f = t + l * 256, r = f >> 5, c = f & 31;
            float4 kvv = *(const float4*)(Kt + r * 128 + c * 4);
            float* kd = Ks + r * 129 + c * 4;
            kd[0] = kvv.x; kd[1] = kvv.y; kd[2] = kvv.z; kd[3] = kvv.w;
            float4 vv = *(const float4*)(Vt + r * 128 + c * 4);
            *(float4*)(Vs + r * 128 + c * 4) = vv;
        }
        __syncthreads();

        // scores: 4 queries x 4 keys per thread
        float sc[4][4];
#pragma unroll
        for (int i = 0; i < 4; i++)
#pragma unroll
            for (int j = 0; j < 4; j++) sc[i][j] = 0.f;

#pragma unroll 4
        for (int d = 0; d < 128; d++) {
            float qv[4], kr[4];
#pragma unroll
            for (int i = 0; i < 4; i++) qv[i] = Qs[(ty * 4 + i) * 129 + d];
#pragma unroll
            for (int j = 0; j < 4; j++) kr[j] = Ks[(tx * 4 + j) * 129 + d];
#pragma unroll
            for (int i = 0; i < 4; i++)
#pragma unroll
                for (int j = 0; j < 4; j++)
                    sc[i][j] = fmaf(qv[i], kr[j], sc[i][j]);
        }

        // online softmax update (row reduce across the 16 tx lanes)
#pragma unroll
        for (int i = 0; i < 4; i++) {
            float rm = fmaxf(fmaxf(sc[i][0], sc[i][1]), fmaxf(sc[i][2], sc[i][3]));
#pragma unroll
            for (int o = 1; o < 16; o <<= 1)
                rm = fmaxf(rm, __shfl_xor_sync(0xffffffffu, rm, o));
            float mn = fmaxf(m_[i], rm);
            float al = __expf(m_[i] - mn);
            float ps = 0.f;
#pragma unroll
            for (int j = 0; j < 4; j++) { sc[i][j] = __expf(sc[i][j] - mn); ps += sc[i][j]; }
#pragma unroll
            for (int o = 1; o < 16; o <<= 1)
                ps += __shfl_xor_sync(0xffffffffu, ps, o);
            l_[i] = l_[i] * al + ps;
            m_[i] = mn;
#pragma unroll
            for (int j = 0; j < 8; j++) o_[i][j] *= al;
            *(float4*)(Ps + (ty * 4 + i) * 68 + tx * 4) =
                make_float4(sc[i][0], sc[i][1], sc[i][2], sc[i][3]);
        }
        __syncwarp();   // Ps producer/consumer are the same warp (same ty group)

        // O += P @ V  (each thread: 4 queries x 8 dims)
#pragma unroll 4
        for (int k = 0; k < 64; k++) {
            float4 v0 = *(const float4*)(Vs + k * 128 + tx * 8);
            float4 v1 = *(const float4*)(Vs + k * 128 + tx * 8 + 4);
#pragma unroll
            for (int i = 0; i < 4; i++) {
                float p = Ps[(ty * 4 + i) * 68 + k];
                o_[i][0] = fmaf(p, v0.x, o_[i][0]);
                o_[i][1] = fmaf(p, v0.y, o_[i][1]);
                o_[i][2] = fmaf(p, v0.z, o_[i][2]);
                o_[i][3] = fmaf(p, v0.w, o_[i][3]);
                o_[i][4] = fmaf(p, v1.x, o_[i][4]);
                o_[i][5] = fmaf(p, v1.y, o_[i][5]);
                o_[i][6] = fmaf(p, v1.z, o_[i][6]);
                o_[i][7] = fmaf(p, v1.w, o_[i][7]);
            }
        }
    }

    // epilogue: normalize, gate, scatter to ctx [b*s][h*128+d]
#pragma unroll
    for (int i = 0; i < 4; i++) {
        float inv = 1.0f / l_[i];
        int qrow = q0 + ty * 4 + i;
        const float* gp = g_gate + ((size_t)((b * S_LEN + qrow) * NH + h)) * HD + tx * 8;
        float* cp = g_ctx + (size_t)(b * S_LEN + qrow) * 1024 + h * HD + tx * 8;
        float4 g0 = *(const float4*)gp;
        float4 g1 = *(const float4*)(gp + 4);
        float4 o0, o1;
        o0.x = o_[i][0] * inv * (1.f / (1.f + __expf(-g0.x)));
        o0.y = o_[i][1] * inv * (1.f / (1.f + __expf(-g0.y)));
        o0.z = o_[i][2] * inv * (1.f / (1.f + __expf(-g0.z)));
        o0.w = o_[i][3] * inv * (1.f / (1.f + __expf(-g0.w)));
        o1.x = o_[i][4] * inv * (1.f / (1.f + __expf(-g1.x)));
        o1.y = o_[i][5] * inv * (1.f / (1.f + __expf(-g1.y)));
        o1.z = o_[i][6] * inv * (1.f / (1.f + __expf(-g1.z)));
        o1.w = o_[i][7] * inv * (1.f / (1.f + __expf(-g1.w)));
        *(float4*)cp = o0;
        *(float4*)(cp + 4) = o1;
    }
}

// ---------------------------------------------------------------------------
extern "C" void kernel_launch(void* const* d_in, const int* in_sizes, int n_in,
                              void* d_out, int out_size)
{
    const float* hidden = (const float*)d_in[0];
    const float* rope   = (const float*)d_in[1];
    const float* Wq     = (const float*)d_in[2];
    const float* bq     = (const float*)d_in[3];
    const float* Wk     = (const float*)d_in[4];
    const float* bk     = (const float*)d_in[5];
    const float* Wv     = (const float*)d_in[6];
    const float* bv     = (const float*)d_in[7];
    const float* Wo     = (const float*)d_in[8];
    const float* bo     = (const float*)d_in[9];
    const float* qw     = (const float*)d_in[10];
    const float* kw     = (const float*)d_in[11];
    float* out = (float*)d_out;

    float *qkv, *ctx;
    cudaGetSymbolAddress((void**)&qkv, g_qkv);
    cudaGetSymbolAddress((void**)&ctx, g_ctx);

    cudaFuncSetAttribute((const void*)attn_kernel,
                         cudaFuncAttributeMaxDynamicSharedMemorySize,
                         SMEM_ATTN_BYTES);

    dim3 blk(256);
    // QKV projections into fused scratch row [qg(2048) | k(256) | v(256)]
    sgemm_bias<<<dim3(16, 64), blk>>>(hidden, Wq, bq, qkv, 2048, 1024, 2560, 0);
    sgemm_bias<<<dim3(2, 64),  blk>>>(hidden, Wk, bk, qkv,  256, 1024, 2560, 2048);
    sgemm_bias<<<dim3(2, 64),  blk>>>(hidden, Wv, bv, qkv,  256, 1024, 2560, 2304);

    transform_kernel<<<M_ROWS, 384>>>(qkv, rope, qw, kw);

    attn_kernel<<<dim3(32, NH, NB), 256, SMEM_ATTN_BYTES>>>();

    sgemm_bias<<<dim3(8, 64), blk>>>(ctx, Wo, bo, out, 1024, 1024, 1024, 0);
}

// round 3
// speedup vs baseline: 1.3773x; 1.3773x over previous
#include <cuda_runtime.h>
#include <math.h>

// Problem constants: B=4, S=2048, HID=1024, H=8, KV=2, HD=128, G=4
#define M_ROWS   8192
#define S_LEN    2048
#define NB       4
#define NH       8
#define NKV      2
#define HD       128

// ---------------- scratch ----------------------------------------------------
__device__ float g_qkv [(size_t)M_ROWS * 2560];
__device__ float g_q   [(size_t)NB * NH  * S_LEN * HD];
__device__ float g_k   [(size_t)NB * NKV * S_LEN * HD];
__device__ float g_v   [(size_t)NB * NKV * S_LEN * HD];
__device__ float g_gate[(size_t)NB * S_LEN * NH * HD];
__device__ float g_ctx [(size_t)M_ROWS * 1024];

// ---------------- tf32 helpers -----------------------------------------------
__device__ __forceinline__ unsigned f2tf32(float x) {
    unsigned y;
    asm("cvt.rna.tf32.f32 %0, %1;" : "=r"(y) : "f"(x));
    return y;
}
// error-compensated split: x ~= hi + lo, residual O(eps_tf32^2 * |x|)
__device__ __forceinline__ void split_tf32(float x, unsigned& hi, unsigned& lo) {
    hi = f2tf32(x);
    lo = f2tf32(x - __uint_as_float(hi));
}

__device__ __forceinline__ void mma_tf32(float* d, const unsigned* a,
                                         const unsigned* b, const float* c) {
    asm volatile(
        "mma.sync.aligned.m16n8k8.row.col.f32.tf32.tf32.f32 "
        "{%0,%1,%2,%3}, {%4,%5,%6,%7}, {%8,%9}, {%10,%11,%12,%13};\n"
        : "=f"(d[0]), "=f"(d[1]), "=f"(d[2]), "=f"(d[3])
        : "r"(a[0]), "r"(a[1]), "r"(a[2]), "r"(a[3]),
          "r"(b[0]), "r"(b[1]),
          "f"(c[0]), "f"(c[1]), "f"(c[2]), "f"(c[3]));
}

__device__ __forceinline__ void cp16(unsigned dst, const void* src) {
    asm volatile("cp.async.cg.shared.global [%0], [%1], 16;\n"
                 :: "r"(dst), "l"(src));
}
#define CP_COMMIT()  asm volatile("cp.async.commit_group;\n")
#define CP_WAIT(n)   asm volatile("cp.async.wait_group %0;\n" :: "n"(n))

// -----------------------------------------------------------------------------
// 3xTF32 GEMM: C[m, ccol0+n] = A[m,:K] @ Bm[:K,n] + bias[n]
// Block tile 128x128, K-step 32, 8 warps (2m x 4n), warp tile 64x32.
// hi/lo split tiles in dynamic smem; register prefetch of next global tile.
// -----------------------------------------------------------------------------
#define GA_W   (128 * 36)
#define GB_W   (32 * 132)
#define GEMM_SMEM_BYTES ((2 * GA_W + 2 * GB_W) * 4)

__global__ __launch_bounds__(256, 1) void gemm_tf32_x3(
    const float* __restrict__ A, const float* __restrict__ Bm,
    const float* __restrict__ bias, float* __restrict__ C,
    int N, int K, int ldc, int ccol0)
{
    extern __shared__ unsigned gsm[];
    unsigned* Ah = gsm;                // [128][36]
    unsigned* Al = Ah + GA_W;
    unsigned* Bh = Al + GA_W;          // [32][132]
    unsigned* Bl = Bh + GB_W;

    const int t    = threadIdx.x;
    const int warp = t >> 5;
    const int lane = t & 31;
    const int wm   = warp >> 2;
    const int wn   = warp & 3;
    const int m0   = blockIdx.y * 128;
    const int n0   = blockIdx.x * 128;
    const int g    = lane >> 2;
    const int c    = lane & 3;

    float acc[4][4][4];
#pragma unroll
    for (int mt = 0; mt < 4; mt++)
#pragma unroll
        for (int nt = 0; nt < 4; nt++)
#pragma unroll
            for (int i = 0; i < 4; i++) acc[mt][nt][i] = 0.f;

    float4 ra[4], rb[4];
#pragma unroll
    for (int l = 0; l < 4; l++) {
        int f = t + l * 256;
        ra[l] = *(const float4*)(A + (size_t)(m0 + (f >> 3)) * K + (f & 7) * 4);
        rb[l] = *(const float4*)(Bm + (size_t)(f >> 5) * N + n0 + (f & 31) * 4);
    }

    for (int k0 = 0; k0 < K; k0 += 32) {
#pragma unroll
        for (int l = 0; l < 4; l++) {
            int f = t + l * 256;
            int ao = (f >> 3) * 36 + (f & 7) * 4;
            split_tf32(ra[l].x, Ah[ao + 0], Al[ao + 0]);
            split_tf32(ra[l].y, Ah[ao + 1], Al[ao + 1]);
            split_tf32(ra[l].z, Ah[ao + 2], Al[ao + 2]);
            split_tf32(ra[l].w, Ah[ao + 3], Al[ao + 3]);
            int bo = (f >> 5) * 132 + (f & 31) * 4;
            split_tf32(rb[l].x, Bh[bo + 0], Bl[bo + 0]);
            split_tf32(rb[l].y, Bh[bo + 1], Bl[bo + 1]);
            split_tf32(rb[l].z, Bh[bo + 2], Bl[bo + 2]);
            split_tf32(rb[l].w, Bh[bo + 3], Bl[bo + 3]);
        }
        __syncthreads();

        if (k0 + 32 < K) {
            int kn = k0 + 32;
#pragma unroll
            for (int l = 0; l < 4; l++) {
                int f = t + l * 256;
                ra[l] = *(const float4*)(A + (size_t)(m0 + (f >> 3)) * K + kn + (f & 7) * 4);
                rb[l] = *(const float4*)(Bm + (size_t)(kn + (f >> 5)) * N + n0 + (f & 31) * 4);
            }
        }

#pragma unroll
        for (int ks = 0; ks < 4; ks++) {
            unsigned afh[4][4], afl[4][4];
#pragma unroll
            for (int mt = 0; mt < 4; mt++) {
                int row = (wm * 64 + mt * 16 + g) * 36 + ks * 8;
                afh[mt][0] = Ah[row + c];
                afh[mt][1] = Ah[row + 8 * 36 + c];
                afh[mt][2] = Ah[row + c + 4];
                afh[mt][3] = Ah[row + 8 * 36 + c + 4];
                afl[mt][0] = Al[row + c];
                afl[mt][1] = Al[row + 8 * 36 + c];
                afl[mt][2] = Al[row + c + 4];
                afl[mt][3] = Al[row + 8 * 36 + c + 4];
            }
            unsigned bfh[4][2], bfl[4][2];
#pragma unroll
            for (int nt = 0; nt < 4; nt++) {
                int col = wn * 32 + nt * 8 + g;
                bfh[nt][0] = Bh[(ks * 8 + c) * 132 + col];
                bfh[nt][1] = Bh[(ks * 8 + c + 4) * 132 + col];
                bfl[nt][0] = Bl[(ks * 8 + c) * 132 + col];
                bfl[nt][1] = Bl[(ks * 8 + c + 4) * 132 + col];
            }
            // three split rounds, spaced to avoid same-acc RAW chains
#pragma unroll
            for (int nt = 0; nt < 4; nt++)
#pragma unroll
                for (int mt = 0; mt < 4; mt++)
                    mma_tf32(acc[mt][nt], afh[mt], bfh[nt], acc[mt][nt]);
#pragma unroll
            for (int nt = 0; nt < 4; nt++)
#pragma unroll
                for (int mt = 0; mt < 4; mt++)
                    mma_tf32(acc[mt][nt], afh[mt], bfl[nt], acc[mt][nt]);
#pragma unroll
            for (int nt = 0; nt < 4; nt++)
#pragma unroll
                for (int mt = 0; mt < 4; mt++)
                    mma_tf32(acc[mt][nt], afl[mt], bfh[nt], acc[mt][nt]);
        }
        __syncthreads();
    }

#pragma unroll
    for (int mt = 0; mt < 4; mt++) {
        int row = m0 + wm * 64 + mt * 16 + g;
#pragma unroll
        for (int nt = 0; nt < 4; nt++) {
            int col = n0 + wn * 32 + nt * 8 + 2 * c;
            float bx = bias[col], by = bias[col + 1];
            float2 o0 = make_float2(acc[mt][nt][0] + bx, acc[mt][nt][1] + by);
            float2 o1 = make_float2(acc[mt][nt][2] + bx, acc[mt][nt][3] + by);
            *(float2*)(C + (size_t)row * ldc + ccol0 + col)       = o0;
            *(float2*)(C + (size_t)(row + 8) * ldc + ccol0 + col) = o1;
        }
    }
}

// -----------------------------------------------------------------------------
// Transform: RMSNorm + RoPE on Q/K heads, copy V and gate. (unchanged)
// -----------------------------------------------------------------------------
__global__ __launch_bounds__(384) void transform_kernel(
    const float* __restrict__ qkv, const float* __restrict__ rope,
    const float* __restrict__ qw,  const float* __restrict__ kw)
{
    const int bs = blockIdx.x;
    const int b  = bs >> 11;
    const int s  = bs & 2047;
    const float* row = qkv + (size_t)bs * 2560;
    const float* emb = rope + (size_t)s * 256;
    const int w    = threadIdx.x >> 5;
    const int lane = threadIdx.x & 31;

    if (w < 10) {
        const bool isq = (w < 8);
        int off, outbase;
        const float* nw;
        if (isq) {
            int kvh = w >> 2;
            off     = kvh * 1024 + (w & 3) * 128;
            nw      = qw;
            outbase = ((b * NH + w) * S_LEN + s) * HD;
        } else {
            int j   = w - 8;
            off     = 2048 + j * 128;
            nw      = kw;
            outbase = ((b * NKV + j) * S_LEN + s) * HD;
        }
        const int d = lane * 4;
        float4 x = *(const float4*)(row + off + d);
        float ss = x.x * x.x + x.y * x.y + x.z * x.z + x.w * x.w;
#pragma unroll
        for (int o = 16; o > 0; o >>= 1) ss += __shfl_xor_sync(0xffffffffu, ss, o);
        float rn = rsqrtf(ss * (1.0f / 128.0f) + 1e-6f);
        float4 wv = *(const float4*)(nw + d);
        x.x *= rn * wv.x; x.y *= rn * wv.y; x.z *= rn * wv.z; x.w *= rn * wv.w;
        float4 sn = *(const float4*)(emb + d);
        float4 cs = *(const float4*)(emb + 128 + d);
        float4 y;
        y.x = x.x * cs.x - x.y * sn.x;
        y.y = x.y * cs.y + x.x * sn.y;
        y.z = x.z * cs.z - x.w * sn.z;
        y.w = x.w * cs.w + x.z * sn.w;
        float* dst = (isq ? g_q : g_k) + outbase + d;
        *(float4*)dst = y;
    } else if (w == 10) {
#pragma unroll
        for (int rr = 0; rr < 2; rr++) {
            int f = lane + rr * 32;
            int j = f >> 5, cc = f & 31;
            float4 v = *(const float4*)(row + 2304 + j * 128 + cc * 4);
            *(float4*)(g_v + ((size_t)((b * NKV + j) * S_LEN + s)) * HD + cc * 4) = v;
        }
    } else {
#pragma unroll
        for (int rr = 0; rr < 8; rr++) {
            int f  = lane + rr * 32;
            int hh = f >> 5, cc = f & 31;
            int src = (hh >> 2) * 1024 + 512 + (hh & 3) * 128 + cc * 4;
            float4 v = *(const float4*)(row + src);
            *(float4*)(g_gate + ((size_t)(bs * NH + hh)) * HD + cc * 4) = v;
        }
    }
}

// -----------------------------------------------------------------------------
// Flash attention, 3xTF32 tensor cores + fused sigmoid gate.
// Block: 64 queries x one (b,h). 4 warps x 16 q-rows. K-tile = 32 keys.
// cp.async double-buffers RAW fp32 K/V; cooperative hi/lo conversion per tile.
// -----------------------------------------------------------------------------
#define QROW_W   132
#define QH_OFF   0
#define QL_OFF   8448                 // 64*132
#define RAW_OFF  16896                // 2 stages x (K 4224 + V 4224)
#define KH_OFF   33792
#define KL_OFF   38016
#define VH_OFF   42240
#define VL_OFF   46464
#define ATT_WORDS 50688
#define ATT_SMEM_BYTES (ATT_WORDS * 4)

__global__ __launch_bounds__(128, 1) void attn_kernel()
{
    extern __shared__ __align__(16) unsigned sm[];
    const unsigned smem_b = (unsigned)__cvta_generic_to_shared(sm);
    unsigned* Qh = sm + QH_OFF;
    unsigned* Ql = sm + QL_OFF;
    unsigned* Kh = sm + KH_OFF;
    unsigned* Kl = sm + KL_OFF;
    unsigned* Vh = sm + VH_OFF;
    unsigned* Vl = sm + VL_OFF;

    const int t    = threadIdx.x;
    const int warp = t >> 5;
    const int lane = t & 31;
    const int g    = lane >> 2;
    const int c    = lane & 3;
    const int b    = blockIdx.z;
    const int h    = blockIdx.y;
    const int q0   = blockIdx.x * 64;
    const int kv   = h >> 2;
    const float scale = 0.08838834764831845f;

    const float* Qg = g_q + ((size_t)((b * NH + h) * S_LEN + q0)) * HD;
    const float* Kb = g_k + ((size_t)(b * NKV + kv)) * S_LEN * HD;
    const float* Vb = g_v + ((size_t)(b * NKV + kv)) * S_LEN * HD;

    // ---- Q load: scale then split ----
#pragma unroll
    for (int l = 0; l < 16; l++) {
        int idx = t + l * 128;
        int r = idx >> 5, c4 = idx & 31;
        float4 v = *(const float4*)(Qg + r * 128 + c4 * 4);
        int o = r * QROW_W + c4 * 4;
        split_tf32(v.x * scale, Qh[o + 0], Ql[o + 0]);
        split_tf32(v.y * scale, Qh[o + 1], Ql[o + 1]);
        split_tf32(v.z * scale, Qh[o + 2], Ql[o + 2]);
        split_tf32(v.w * scale, Qh[o + 3], Ql[o + 3]);
    }

    auto issue = [&](int kt, int buf) {
        const float* Kt = Kb + (size_t)kt * 32 * 128;
        const float* Vt = Vb + (size_t)kt * 32 * 128;
        unsigned base = smem_b + (RAW_OFF + buf * 8448) * 4;
#pragma unroll
        for (int l = 0; l < 8; l++) {
            int idx = t + l * 128;
            int r = idx >> 5, c4 = idx & 31;
            unsigned off = (r * QROW_W + c4 * 4) * 4;
            cp16(base + off,              Kt + r * 128 + c4 * 4);
            cp16(base + 4224 * 4 + off,   Vt + r * 128 + c4 * 4);
        }
    };

    issue(0, 0);
    CP_COMMIT();

    float o[16][4];
#pragma unroll
    for (int nt = 0; nt < 16; nt++)
#pragma unroll
        for (int i = 0; i < 4; i++) o[nt][i] = 0.f;
    float m0 = -1e30f, m1 = -1e30f, l0 = 0.f, l1 = 0.f;

    const int qoff  = (warp * 16 + g) * QROW_W;
    const int srcb  = lane & ~3;
    const int src0  = srcb + (c >> 1);
    const int src2  = src0 + 2;
    const bool odd  = (c & 1);

    for (int kt = 0; kt < 64; kt++) {
        if (kt < 63) { issue(kt + 1, (kt + 1) & 1); CP_COMMIT(); CP_WAIT(1); }
        else         { CP_WAIT(0); }
        __syncthreads();   // staging ready + prev compute done with hi/lo tiles

        // ---- cooperative split of K/V tile ----
        const unsigned* Raw = sm + RAW_OFF + (kt & 1) * 8448;
#pragma unroll
        for (int l = 0; l < 8; l++) {
            int idx = t + l * 128;
            int r = idx >> 5, c4 = idx & 31;
            int off = r * QROW_W + c4 * 4;
            float4 kk = *(const float4*)(Raw + off);
            split_tf32(kk.x, Kh[off + 0], Kl[off + 0]);
            split_tf32(kk.y, Kh[off + 1], Kl[off + 1]);
            split_tf32(kk.z, Kh[off + 2], Kl[off + 2]);
            split_tf32(kk.w, Kh[off + 3], Kl[off + 3]);
            float4 vv = *(const float4*)(Raw + 4224 + off);
            split_tf32(vv.x, Vh[off + 0], Vl[off + 0]);
            split_tf32(vv.y, Vh[off + 1], Vl[off + 1]);
            split_tf32(vv.z, Vh[off + 2], Vl[off + 2]);
            split_tf32(vv.w, Vh[off + 3], Vl[off + 3]);
        }
        __syncthreads();

        // ---- scores S = Q K^T  (warp: 16 rows x 32 keys) ----
        float sc[4][4];
#pragma unroll
        for (int nt = 0; nt < 4; nt++)
#pragma unroll
            for (int i = 0; i < 4; i++) sc[nt][i] = 0.f;

#pragma unroll
        for (int ks = 0; ks < 16; ks++) {
            unsigned ah[4], al[4];
            ah[0] = Qh[qoff + ks * 8 + c];
            ah[1] = Qh[qoff + 8 * QROW_W + ks * 8 + c];
            ah[2] = Qh[qoff + ks * 8 + c + 4];
            ah[3] = Qh[qoff + 8 * QROW_W + ks * 8 + c + 4];
            al[0] = Ql[qoff + ks * 8 + c];
            al[1] = Ql[qoff + 8 * QROW_W + ks * 8 + c];
            al[2] = Ql[qoff + ks * 8 + c + 4];
            al[3] = Ql[qoff + 8 * QROW_W + ks * 8 + c + 4];
            unsigned bfh[4][2], bfl[4][2];
#pragma unroll
            for (int nt = 0; nt < 4; nt++) {
                int ko = (nt * 8 + g) * QROW_W + ks * 8 + c;
                bfh[nt][0] = Kh[ko]; bfh[nt][1] = Kh[ko + 4];
                bfl[nt][0] = Kl[ko]; bfl[nt][1] = Kl[ko + 4];
            }
#pragma unroll
            for (int nt = 0; nt < 4; nt++) mma_tf32(sc[nt], ah, bfh[nt], sc[nt]);
#pragma unroll
            for (int nt = 0; nt < 4; nt++) mma_tf32(sc[nt], ah, bfl[nt], sc[nt]);
#pragma unroll
            for (int nt = 0; nt < 4; nt++) mma_tf32(sc[nt], al, bfh[nt], sc[nt]);
        }

        // ---- online softmax (rows g, g+8) ----
        float t0 = -1e30f, t1 = -1e30f;
#pragma unroll
        for (int nt = 0; nt < 4; nt++) {
            t0 = fmaxf(t0, fmaxf(sc[nt][0], sc[nt][1]));
            t1 = fmaxf(t1, fmaxf(sc[nt][2], sc[nt][3]));
        }
        t0 = fmaxf(t0, __shfl_xor_sync(0xffffffffu, t0, 1));
        t0 = fmaxf(t0, __shfl_xor_sync(0xffffffffu, t0, 2));
        t1 = fmaxf(t1, __shfl_xor_sync(0xffffffffu, t1, 1));
        t1 = fmaxf(t1, __shfl_xor_sync(0xffffffffu, t1, 2));
        float mn0 = fmaxf(m0, t0), mn1 = fmaxf(m1, t1);
        float al0 = __expf(m0 - mn0), al1 = __expf(m1 - mn1);
        m0 = mn0; m1 = mn1;
        float s0 = 0.f, s1 = 0.f;
#pragma unroll
        for (int nt = 0; nt < 4; nt++) {
            sc[nt][0] = __expf(sc[nt][0] - mn0); s0 += sc[nt][0];
            sc[nt][1] = __expf(sc[nt][1] - mn0); s0 += sc[nt][1];
            sc[nt][2] = __expf(sc[nt][2] - mn1); s1 += sc[nt][2];
            sc[nt][3] = __expf(sc[nt][3] - mn1); s1 += sc[nt][3];
        }
        s0 += __shfl_xor_sync(0xffffffffu, s0, 1);
        s0 += __shfl_xor_sync(0xffffffffu, s0, 2);
        s1 += __shfl_xor_sync(0xffffffffu, s1, 1);
        s1 += __shfl_xor_sync(0xffffffffu, s1, 2);
        l0 = l0 * al0 + s0;
        l1 = l1 * al1 + s1;
#pragma unroll
        for (int nt = 0; nt < 16; nt++) {
            o[nt][0] *= al0; o[nt][1] *= al0;
            o[nt][2] *= al1; o[nt][3] *= al1;
        }

        // ---- O += P V : C-frag -> A-frag shuffle, split P and V ----
#pragma unroll
        for (int ks = 0; ks < 4; ks++) {
            float t00 = __shfl_sync(0xffffffffu, sc[ks][0], src0);
            float t01 = __shfl_sync(0xffffffffu, sc[ks][1], src0);
            float t10 = __shfl_sync(0xffffffffu, sc[ks][2], src0);
            float t11 = __shfl_sync(0xffffffffu, sc[ks][3], src0);
            float t20 = __shfl_sync(0xffffffffu, sc[ks][0], src2);
            float t21 = __shfl_sync(0xffffffffu, sc[ks][1], src2);
            float t30 = __shfl_sync(0xffffffffu, sc[ks][2], src2);
            float t31 = __shfl_sync(0xffffffffu, sc[ks][3], src2);
            unsigned ah[4], al[4];
            split_tf32(odd ? t01 : t00, ah[0], al[0]);
            split_tf32(odd ? t11 : t10, ah[1], al[1]);
            split_tf32(odd ? t21 : t20, ah[2], al[2]);
            split_tf32(odd ? t31 : t30, ah[3], al[3]);
            unsigned bfh[16][2], bfl[16][2];
#pragma unroll
            for (int nt = 0; nt < 16; nt++) {
                int vo = (ks * 8 + c) * QROW_W + nt * 8 + g;
                bfh[nt][0] = Vh[vo]; bfh[nt][1] = Vh[vo + 4 * QROW_W];
                bfl[nt][0] = Vl[vo]; bfl[nt][1] = Vl[vo + 4 * QROW_W];
            }
#pragma unroll
            for (int nt = 0; nt < 16; nt++) mma_tf32(o[nt], ah, bfh[nt], o[nt]);
#pragma unroll
            for (int nt = 0; nt < 16; nt++) mma_tf32(o[nt], ah, bfl[nt], o[nt]);
#pragma unroll
            for (int nt = 0; nt < 16; nt++) mma_tf32(o[nt], al, bfh[nt], o[nt]);
        }
        __syncthreads();
    }

    // ---- epilogue: normalize, sigmoid-gate, store ----
    float inv0 = 1.f / l0, inv1 = 1.f / l1;
    int qrow0 = q0 + warp * 16 + g;
    int qrow1 = qrow0 + 8;
    const float* g0p = g_gate + ((size_t)((b * S_LEN + qrow0) * NH + h)) * HD;
    const float* g1p = g_gate + ((size_t)((b * S_LEN + qrow1) * NH + h)) * HD;
    float* c0p = g_ctx + (size_t)(b * S_LEN + qrow0) * 1024 + h * HD;
    float* c1p = g_ctx + (size_t)(b * S_LEN + qrow1) * 1024 + h * HD;
#pragma unroll
    for (int nt = 0; nt < 16; nt++) {
        int d = nt * 8 + 2 * c;
        float2 gA = *(const float2*)(g0p + d);
        float2 oA;
        oA.x = o[nt][0] * inv0 * (1.f / (1.f + __expf(-gA.x)));
        oA.y = o[nt][1] * inv0 * (1.f / (1.f + __expf(-gA.y)));
        *(float2*)(c0p + d) = oA;
        float2 gB = *(const float2*)(g1p + d);
        float2 oB;
        oB.x = o[nt][2] * inv1 * (1.f / (1.f + __expf(-gB.x)));
        oB.y = o[nt][3] * inv1 * (1.f / (1.f + __expf(-gB.y)));
        *(float2*)(c1p + d) = oB;
    }
}

// -----------------------------------------------------------------------------
extern "C" void kernel_launch(void* const* d_in, const int* in_sizes, int n_in,
                              void* d_out, int out_size)
{
    const float* hidden = (const float*)d_in[0];
    const float* rope   = (const float*)d_in[1];
    const float* Wq     = (const float*)d_in[2];
    const float* bq     = (const float*)d_in[3];
    const float* Wk     = (const float*)d_in[4];
    const float* bk     = (const float*)d_in[5];
    const float* Wv     = (const float*)d_in[6];
    const float* bv     = (const float*)d_in[7];
    const float* Wo     = (const float*)d_in[8];
    const float* bo     = (const float*)d_in[9];
    const float* qw     = (const float*)d_in[10];
    const float* kw     = (const float*)d_in[11];
    float* out = (float*)d_out;

    float *qkv, *ctx;
    cudaGetSymbolAddress((void**)&qkv, g_qkv);
    cudaGetSymbolAddress((void**)&ctx, g_ctx);

    cudaFuncSetAttribute((const void*)gemm_tf32_x3,
                         cudaFuncAttributeMaxDynamicSharedMemorySize,
                         GEMM_SMEM_BYTES);
    cudaFuncSetAttribute((const void*)attn_kernel,
                         cudaFuncAttributeMaxDynamicSharedMemorySize,
                         ATT_SMEM_BYTES);

    dim3 blk(256);
    gemm_tf32_x3<<<dim3(16, 64), blk, GEMM_SMEM_BYTES>>>(hidden, Wq, bq, qkv, 2048, 1024, 2560, 0);
    gemm_tf32_x3<<<dim3(2, 64),  blk, GEMM_SMEM_BYTES>>>(hidden, Wk, bk, qkv,  256, 1024, 2560, 2048);
    gemm_tf32_x3<<<dim3(2, 64),  blk, GEMM_SMEM_BYTES>>>(hidden, Wv, bv, qkv,  256, 1024, 2560, 2304);

    transform_kernel<<<M_ROWS, 384>>>(qkv, rope, qw, kw);

    attn_kernel<<<dim3(32, NH, NB), 128, ATT_SMEM_BYTES>>>();

    gemm_tf32_x3<<<dim3(8, 64), blk, GEMM_SMEM_BYTES>>>(ctx, Wo, bo, out, 1024, 1024, 1024, 0);
}

// round 4
// speedup vs baseline: 2.5114x; 1.8234x over previous
#include <cuda_runtime.h>
#include <math.h>

// Problem constants: B=4, S=2048, HID=1024, H=8, KV=2, HD=128, G=4
#define M_ROWS   8192
#define S_LEN    2048
#define NB       4
#define NH       8
#define NKV      2
#define HD       128

// ---------------- scratch ----------------------------------------------------
__device__ float g_qkv [(size_t)M_ROWS * 2560];
__device__ float g_q   [(size_t)NB * NH  * S_LEN * HD];
__device__ float g_k   [(size_t)NB * NKV * S_LEN * HD];
__device__ float g_v   [(size_t)NB * NKV * S_LEN * HD];
__device__ float g_gate[(size_t)NB * S_LEN * NH * HD];
__device__ float g_ctx [(size_t)M_ROWS * 1024];

// ---------------- bf16 split helpers ------------------------------------------
// pack two floats into one bf16x2 word: low half = x0, high half = x1
// split: x ~= hi + lo (each bf16) -> ~16 effective mantissa bits
__device__ __forceinline__ void split_pair(float x0, float x1,
                                           unsigned& hi, unsigned& lo) {
    unsigned h;
    asm("cvt.rn.bf16x2.f32 %0, %1, %2;" : "=r"(h) : "f"(x1), "f"(x0));
    float r0 = x0 - __uint_as_float(h << 16);
    float r1 = x1 - __uint_as_float(h & 0xffff0000u);
    unsigned l;
    asm("cvt.rn.bf16x2.f32 %0, %1, %2;" : "=r"(l) : "f"(r1), "f"(r0));
    hi = h; lo = l;
}

__device__ __forceinline__ void mma_bf16(float* d, const unsigned* a,
                                         const unsigned* b, const float* c) {
    asm volatile(
        "mma.sync.aligned.m16n8k16.row.col.f32.bf16.bf16.f32 "
        "{%0,%1,%2,%3}, {%4,%5,%6,%7}, {%8,%9}, {%10,%11,%12,%13};\n"
        : "=f"(d[0]), "=f"(d[1]), "=f"(d[2]), "=f"(d[3])
        : "r"(a[0]), "r"(a[1]), "r"(a[2]), "r"(a[3]),
          "r"(b[0]), "r"(b[1]),
          "f"(c[0]), "f"(c[1]), "f"(c[2]), "f"(c[3]));
}

// -----------------------------------------------------------------------------
// 3xBF16 GEMM: C[m, ccol0+n] = A[m,:K] @ Bm[:K,n] + bias[n]
// Block tile 128x128, K-step 32, 8 warps (2m x 4n), warp tile 64x32.
// smem holds packed bf16x2 hi/lo tiles (pairs along k). Register prefetch.
// -----------------------------------------------------------------------------
#define AP_W 2560   // 128 rows * pitch 20 (16 data words + 4 pad)
#define BP_W 2112   // 16 pair-rows * pitch 132

__global__ __launch_bounds__(256, 1) void gemm_bf16x3(
    const float* __restrict__ A, const float* __restrict__ Bm,
    const float* __restrict__ bias, float* __restrict__ C,
    int N, int K, int ldc, int ccol0)
{
    __shared__ unsigned Ah[AP_W], Al[AP_W], Bh[BP_W], Bl[BP_W];

    const int t    = threadIdx.x;
    const int warp = t >> 5;
    const int lane = t & 31;
    const int wm   = warp >> 2;
    const int wn   = warp & 3;
    const int m0   = blockIdx.y * 128;
    const int n0   = blockIdx.x * 128;
    const int g    = lane >> 2;
    const int c    = lane & 3;

    float acc[4][4][4];
#pragma unroll
    for (int mt = 0; mt < 4; mt++)
#pragma unroll
        for (int nt = 0; nt < 4; nt++)
#pragma unroll
            for (int i = 0; i < 4; i++) acc[mt][nt][i] = 0.f;

    float4 ra[4], rb0[2], rb1[2];
    // prefetch k0 = 0
#pragma unroll
    for (int l = 0; l < 4; l++) {
        int idx = t + l * 256;
        ra[l] = *(const float4*)(A + (size_t)(m0 + (idx >> 3)) * K + 4 * (idx & 7));
    }
#pragma unroll
    for (int l = 0; l < 2; l++) {
        int idx = t + l * 256;
        int pr = idx >> 5, cb = 4 * (idx & 31);
        rb0[l] = *(const float4*)(Bm + (size_t)(2 * pr)     * N + n0 + cb);
        rb1[l] = *(const float4*)(Bm + (size_t)(2 * pr + 1) * N + n0 + cb);
    }

    for (int k0 = 0; k0 < K; k0 += 32) {
        // split prefetched regs -> packed smem
#pragma unroll
        for (int l = 0; l < 4; l++) {
            int idx = t + l * 256;
            int o = (idx >> 3) * 20 + 2 * (idx & 7);
            split_pair(ra[l].x, ra[l].y, Ah[o],     Al[o]);
            split_pair(ra[l].z, ra[l].w, Ah[o + 1], Al[o + 1]);
        }
#pragma unroll
        for (int l = 0; l < 2; l++) {
            int idx = t + l * 256;
            int o = (idx >> 5) * 132 + 4 * (idx & 31);
            split_pair(rb0[l].x, rb1[l].x, Bh[o],     Bl[o]);
            split_pair(rb0[l].y, rb1[l].y, Bh[o + 1], Bl[o + 1]);
            split_pair(rb0[l].z, rb1[l].z, Bh[o + 2], Bl[o + 2]);
            split_pair(rb0[l].w, rb1[l].w, Bh[o + 3], Bl[o + 3]);
        }
        __syncthreads();

        if (k0 + 32 < K) {
            int kn = k0 + 32;
#pragma unroll
            for (int l = 0; l < 4; l++) {
                int idx = t + l * 256;
                ra[l] = *(const float4*)(A + (size_t)(m0 + (idx >> 3)) * K + kn + 4 * (idx & 7));
            }
#pragma unroll
            for (int l = 0; l < 2; l++) {
                int idx = t + l * 256;
                int pr = idx >> 5, cb = 4 * (idx & 31);
                rb0[l] = *(const float4*)(Bm + (size_t)(kn + 2 * pr)     * N + n0 + cb);
                rb1[l] = *(const float4*)(Bm + (size_t)(kn + 2 * pr + 1) * N + n0 + cb);
            }
        }

#pragma unroll
        for (int ks = 0; ks < 2; ks++) {
            unsigned afh[4][4], afl[4][4];
#pragma unroll
            for (int mt = 0; mt < 4; mt++) {
                int rw = (wm * 64 + mt * 16 + g) * 20 + ks * 8;
                afh[mt][0] = Ah[rw + c];       afh[mt][1] = Ah[rw + 160 + c];
                afh[mt][2] = Ah[rw + c + 4];   afh[mt][3] = Ah[rw + 160 + c + 4];
                afl[mt][0] = Al[rw + c];       afl[mt][1] = Al[rw + 160 + c];
                afl[mt][2] = Al[rw + c + 4];   afl[mt][3] = Al[rw + 160 + c + 4];
            }
            unsigned bfh[4][2], bfl[4][2];
#pragma unroll
            for (int nt = 0; nt < 4; nt++) {
                int col = wn * 32 + nt * 8 + g;
                bfh[nt][0] = Bh[(ks * 8 + c) * 132 + col];
                bfh[nt][1] = Bh[(ks * 8 + c + 4) * 132 + col];
                bfl[nt][0] = Bl[(ks * 8 + c) * 132 + col];
                bfl[nt][1] = Bl[(ks * 8 + c + 4) * 132 + col];
            }
#pragma unroll
            for (int nt = 0; nt < 4; nt++)
#pragma unroll
                for (int mt = 0; mt < 4; mt++)
                    mma_bf16(acc[mt][nt], afh[mt], bfh[nt], acc[mt][nt]);
#pragma unroll
            for (int nt = 0; nt < 4; nt++)
#pragma unroll
                for (int mt = 0; mt < 4; mt++)
                    mma_bf16(acc[mt][nt], afh[mt], bfl[nt], acc[mt][nt]);
#pragma unroll
            for (int nt = 0; nt < 4; nt++)
#pragma unroll
                for (int mt = 0; mt < 4; mt++)
                    mma_bf16(acc[mt][nt], afl[mt], bfh[nt], acc[mt][nt]);
        }
        __syncthreads();
    }

#pragma unroll
    for (int mt = 0; mt < 4; mt++) {
        int row = m0 + wm * 64 + mt * 16 + g;
#pragma unroll
        for (int nt = 0; nt < 4; nt++) {
            int col = n0 + wn * 32 + nt * 8 + 2 * c;
            float bx = bias[col], by = bias[col + 1];
            float2 o0 = make_float2(acc[mt][nt][0] + bx, acc[mt][nt][1] + by);
            float2 o1 = make_float2(acc[mt][nt][2] + bx, acc[mt][nt][3] + by);
            *(float2*)(C + (size_t)row * ldc + ccol0 + col)       = o0;
            *(float2*)(C + (size_t)(row + 8) * ldc + ccol0 + col) = o1;
        }
    }
}

// -----------------------------------------------------------------------------
// Transform: RMSNorm + RoPE on Q/K heads, copy V and gate. (unchanged)
// -----------------------------------------------------------------------------
__global__ __launch_bounds__(384) void transform_kernel(
    const float* __restrict__ qkv, const float* __restrict__ rope,
    const float* __restrict__ qw,  const float* __restrict__ kw)
{
    const int bs = blockIdx.x;
    const int b  = bs >> 11;
    const int s  = bs & 2047;
    const float* row = qkv + (size_t)bs * 2560;
    const float* emb = rope + (size_t)s * 256;
    const int w    = threadIdx.x >> 5;
    const int lane = threadIdx.x & 31;

    if (w < 10) {
        const bool isq = (w < 8);
        int off, outbase;
        const float* nw;
        if (isq) {
            int kvh = w >> 2;
            off     = kvh * 1024 + (w & 3) * 128;
            nw      = qw;
            outbase = ((b * NH + w) * S_LEN + s) * HD;
        } else {
            int j   = w - 8;
            off     = 2048 + j * 128;
            nw      = kw;
            outbase = ((b * NKV + j) * S_LEN + s) * HD;
        }
        const int d = lane * 4;
        float4 x = *(const float4*)(row + off + d);
        float ss = x.x * x.x + x.y * x.y + x.z * x.z + x.w * x.w;
#pragma unroll
        for (int o = 16; o > 0; o >>= 1) ss += __shfl_xor_sync(0xffffffffu, ss, o);
        float rn = rsqrtf(ss * (1.0f / 128.0f) + 1e-6f);
        float4 wv = *(const float4*)(nw + d);
        x.x *= rn * wv.x; x.y *= rn * wv.y; x.z *= rn * wv.z; x.w *= rn * wv.w;
        float4 sn = *(const float4*)(emb + d);
        float4 cs = *(const float4*)(emb + 128 + d);
        float4 y;
        y.x = x.x * cs.x - x.y * sn.x;
        y.y = x.y * cs.y + x.x * sn.y;
        y.z = x.z * cs.z - x.w * sn.z;
        y.w = x.w * cs.w + x.z * sn.w;
        float* dst = (isq ? g_q : g_k) + outbase + d;
        *(float4*)dst = y;
    } else if (w == 10) {
#pragma unroll
        for (int rr = 0; rr < 2; rr++) {
            int f = lane + rr * 32;
            int j = f >> 5, cc = f & 31;
            float4 v = *(const float4*)(row + 2304 + j * 128 + cc * 4);
            *(float4*)(g_v + ((size_t)((b * NKV + j) * S_LEN + s)) * HD + cc * 4) = v;
        }
    } else {
#pragma unroll
        for (int rr = 0; rr < 8; rr++) {
            int f  = lane + rr * 32;
            int hh = f >> 5, cc = f & 31;
            int src = (hh >> 2) * 1024 + 512 + (hh & 3) * 128 + cc * 4;
            float4 v = *(const float4*)(row + src);
            *(float4*)(g_gate + ((size_t)(bs * NH + hh)) * HD + cc * 4) = v;
        }
    }
}

// -----------------------------------------------------------------------------
// Flash attention, 3xBF16 tensor cores + fused sigmoid gate.
// Block: 128 queries x one (b,h). 8 warps x 16 q-rows. K-tile = 32 keys.
// K/V register-prefetched (LDG), split into double-buffered packed smem tiles.
// P -> A-fragment conversion is register-only (C-frag layout == A-frag k16).
// smem (words):
//   Qh[128][68] Ql[128][68]          : 0 .. 17408
//   stage s: Kh[32][68] Kl[32][68]   : 17408 + s*4352
//   stage s: Vh[128][20] Vl[128][20] : 26112 + s*5120   (V packed key-pairs)
// -----------------------------------------------------------------------------
#define QH_OFF 0
#define QL_OFF 8704
#define KS_OFF 17408
#define KS_STR 4352
#define VS_OFF 26112
#define VS_STR 5120
#define ATT_WORDS 36352
#define ATT_SMEM_BYTES (ATT_WORDS * 4)

__global__ __launch_bounds__(256, 1) void attn_kernel()
{
    extern __shared__ __align__(16) unsigned sm[];

    const int t    = threadIdx.x;
    const int warp = t >> 5;
    const int lane = t & 31;
    const int g    = lane >> 2;
    const int c    = lane & 3;
    const int b    = blockIdx.z;
    const int h    = blockIdx.y;
    const int q0   = blockIdx.x * 128;
    const int kv   = h >> 2;
    const float scale = 0.08838834764831845f;

    const float* Qg = g_q + ((size_t)((b * NH + h) * S_LEN + q0)) * HD;
    const float* Kb = g_k + ((size_t)(b * NKV + kv)) * S_LEN * HD;
    const float* Vb = g_v + ((size_t)(b * NKV + kv)) * S_LEN * HD;

    // prefetch tile 0 (K: 4 float4/thread, V: 2x2 float4/thread)
    float4 rk[4], rva[2], rvb[2];
    {
        const int r  = t >> 3;
        const int pr = t >> 4;
#pragma unroll
        for (int l = 0; l < 4; l++)
            rk[l] = *(const float4*)(Kb + (size_t)r * 128 + 4 * ((t & 7) + 8 * l));
#pragma unroll
        for (int l = 0; l < 2; l++) {
            int cb = 4 * ((t & 15) + 16 * l);
            rva[l] = *(const float4*)(Vb + (size_t)(2 * pr)     * 128 + cb);
            rvb[l] = *(const float4*)(Vb + (size_t)(2 * pr + 1) * 128 + cb);
        }
    }

    // Q load: scale + split into packed words
    unsigned* Qh = sm + QH_OFF;
    unsigned* Ql = sm + QL_OFF;
#pragma unroll
    for (int i = 0; i < 16; i++) {
        int idx = t + i * 256;
        int r = idx >> 5, c4 = idx & 31;
        float4 v = *(const float4*)(Qg + (size_t)r * 128 + 4 * c4);
        int o = r * 68 + 2 * c4;
        split_pair(v.x * scale, v.y * scale, Qh[o],     Ql[o]);
        split_pair(v.z * scale, v.w * scale, Qh[o + 1], Ql[o + 1]);
    }

    float o_[16][4];
#pragma unroll
    for (int nt = 0; nt < 16; nt++)
#pragma unroll
        for (int i = 0; i < 4; i++) o_[nt][i] = 0.f;
    float m0 = -1e30f, m1 = -1e30f, l0 = 0.f, l1 = 0.f;

    const int qbase = (warp * 16 + g) * 68;

    for (int kt = 0; kt < 64; kt++) {
        // split prefetched regs -> stage[kt&1]
        {
            unsigned* Kh = sm + KS_OFF + (kt & 1) * KS_STR;
            unsigned* Kl = Kh + 2176;
            unsigned* Vh = sm + VS_OFF + (kt & 1) * VS_STR;
            unsigned* Vl = Vh + 2560;
            const int r  = t >> 3;
            const int pr = t >> 4;
#pragma unroll
            for (int l = 0; l < 4; l++) {
                int o = r * 68 + 2 * ((t & 7) + 8 * l);
                split_pair(rk[l].x, rk[l].y, Kh[o],     Kl[o]);
                split_pair(rk[l].z, rk[l].w, Kh[o + 1], Kl[o + 1]);
            }
#pragma unroll
            for (int l = 0; l < 2; l++) {
                int cb = 4 * ((t & 15) + 16 * l);
                split_pair(rva[l].x, rvb[l].x, Vh[(cb + 0) * 20 + pr], Vl[(cb + 0) * 20 + pr]);
                split_pair(rva[l].y, rvb[l].y, Vh[(cb + 1) * 20 + pr], Vl[(cb + 1) * 20 + pr]);
                split_pair(rva[l].z, rvb[l].z, Vh[(cb + 2) * 20 + pr], Vl[(cb + 2) * 20 + pr]);
                split_pair(rva[l].w, rvb[l].w, Vh[(cb + 3) * 20 + pr], Vl[(cb + 3) * 20 + pr]);
            }
        }
        __syncthreads();

        // prefetch next tile
        if (kt < 63) {
            const float* Kt = Kb + (size_t)(kt + 1) * 32 * 128;
            const float* Vt = Vb + (size_t)(kt + 1) * 32 * 128;
            const int r  = t >> 3;
            const int pr = t >> 4;
#pragma unroll
            for (int l = 0; l < 4; l++)
                rk[l] = *(const float4*)(Kt + (size_t)r * 128 + 4 * ((t & 7) + 8 * l));
#pragma unroll
            for (int l = 0; l < 2; l++) {
                int cb = 4 * ((t & 15) + 16 * l);
                rva[l] = *(const float4*)(Vt + (size_t)(2 * pr)     * 128 + cb);
                rvb[l] = *(const float4*)(Vt + (size_t)(2 * pr + 1) * 128 + cb);
            }
        }

        const unsigned* Kh = sm + KS_OFF + (kt & 1) * KS_STR;
        const unsigned* Kl = Kh + 2176;
        const unsigned* Vh = sm + VS_OFF + (kt & 1) * VS_STR;
        const unsigned* Vl = Vh + 2560;

        // ---- scores S = Q K^T (warp: 16 q x 32 keys), 3xBF16 ----
        float sc[4][4];
#pragma unroll
        for (int nt = 0; nt < 4; nt++)
#pragma unroll
            for (int i = 0; i < 4; i++) sc[nt][i] = 0.f;

#pragma unroll
        for (int ks = 0; ks < 8; ks++) {
            unsigned ah[4], al[4];
            ah[0] = Qh[qbase + ks * 8 + c];
            ah[1] = Qh[qbase + 8 * 68 + ks * 8 + c];
            ah[2] = Qh[qbase + ks * 8 + c + 4];
            ah[3] = Qh[qbase + 8 * 68 + ks * 8 + c + 4];
            al[0] = Ql[qbase + ks * 8 + c];
            al[1] = Ql[qbase + 8 * 68 + ks * 8 + c];
            al[2] = Ql[qbase + ks * 8 + c + 4];
            al[3] = Ql[qbase + 8 * 68 + ks * 8 + c + 4];
#pragma unroll
            for (int nt = 0; nt < 4; nt++) {
                int kb = (nt * 8 + g) * 68 + ks * 8;
                unsigned bh[2] = { Kh[kb + c], Kh[kb + c + 4] };
                unsigned bl[2] = { Kl[kb + c], Kl[kb + c + 4] };
                mma_bf16(sc[nt], ah, bh, sc[nt]);
                mma_bf16(sc[nt], ah, bl, sc[nt]);
                mma_bf16(sc[nt], al, bh, sc[nt]);
            }
        }

        // ---- online softmax (rows g, g+8) ----
        float t0 = -1e30f, t1 = -1e30f;
#pragma unroll
        for (int nt = 0; nt < 4; nt++) {
            t0 = fmaxf(t0, fmaxf(sc[nt][0], sc[nt][1]));
            t1 = fmaxf(t1, fmaxf(sc[nt][2], sc[nt][3]));
        }
        t0 = fmaxf(t0, __shfl_xor_sync(0xffffffffu, t0, 1));
        t0 = fmaxf(t0, __shfl_xor_sync(0xffffffffu, t0, 2));
        t1 = fmaxf(t1, __shfl_xor_sync(0xffffffffu, t1, 1));
        t1 = fmaxf(t1, __shfl_xor_sync(0xffffffffu, t1, 2));
        float mn0 = fmaxf(m0, t0), mn1 = fmaxf(m1, t1);
        float al0 = __expf(m0 - mn0), al1 = __expf(m1 - mn1);
        m0 = mn0; m1 = mn1;
        float s0 = 0.f, s1 = 0.f;
#pragma unroll
        for (int nt = 0; nt < 4; nt++) {
            sc[nt][0] = __expf(sc[nt][0] - mn0); s0 += sc[nt][0];
            sc[nt][1] = __expf(sc[nt][1] - mn0); s0 += sc[nt][1];
            sc[nt][2] = __expf(sc[nt][2] - mn1); s1 += sc[nt][2];
            sc[nt][3] = __expf(sc[nt][3] - mn1); s1 += sc[nt][3];
        }
        s0 += __shfl_xor_sync(0xffffffffu, s0, 1);
        s0 += __shfl_xor_sync(0xffffffffu, s0, 2);
        s1 += __shfl_xor_sync(0xffffffffu, s1, 1);
        s1 += __shfl_xor_sync(0xffffffffu, s1, 2);
        l0 = l0 * al0 + s0;
        l1 = l1 * al1 + s1;
#pragma unroll
        for (int nt = 0; nt < 16; nt++) {
            o_[nt][0] *= al0; o_[nt][1] *= al0;
            o_[nt][2] *= al1; o_[nt][3] *= al1;
        }

        // ---- O += P V : P's C-fragment IS the k16 A-fragment ----
#pragma unroll
        for (int ks = 0; ks < 2; ks++) {
            unsigned ah[4], al[4];
            split_pair(sc[2 * ks][0],     sc[2 * ks][1],     ah[0], al[0]);
            split_pair(sc[2 * ks][2],     sc[2 * ks][3],     ah[1], al[1]);
            split_pair(sc[2 * ks + 1][0], sc[2 * ks + 1][1], ah[2], al[2]);
            split_pair(sc[2 * ks + 1][2], sc[2 * ks + 1][3], ah[3], al[3]);
#pragma unroll
            for (int nt = 0; nt < 16; nt++) {
                int vb2 = (nt * 8 + g) * 20 + ks * 8;
                unsigned bh[2] = { Vh[vb2 + c], Vh[vb2 + c + 4] };
                unsigned bl[2] = { Vl[vb2 + c], Vl[vb2 + c + 4] };
                mma_bf16(o_[nt], ah, bh, o_[nt]);
                mma_bf16(o_[nt], ah, bl, o_[nt]);
                mma_bf16(o_[nt], al, bh, o_[nt]);
            }
        }
        __syncthreads();
    }

    // ---- epilogue: normalize, sigmoid-gate, store ----
    float inv0 = 1.f / l0, inv1 = 1.f / l1;
    int qrow0 = q0 + warp * 16 + g;
    int qrow1 = qrow0 + 8;
    const float* g0p = g_gate + ((size_t)((b * S_LEN + qrow0) * NH + h)) * HD;
    const float* g1p = g_gate + ((size_t)((b * S_LEN + qrow1) * NH + h)) * HD;
    float* c0p = g_ctx + (size_t)(b * S_LEN + qrow0) * 1024 + h * HD;
    float* c1p = g_ctx + (size_t)(b * S_LEN + qrow1) * 1024 + h * HD;
#pragma unroll
    for (int nt = 0; nt < 16; nt++) {
        int d = nt * 8 + 2 * c;
        float2 gA = *(const float2*)(g0p + d);
        float2 oA;
        oA.x = o_[nt][0] * inv0 * (1.f / (1.f + __expf(-gA.x)));
        oA.y = o_[nt][1] * inv0 * (1.f / (1.f + __expf(-gA.y)));
        *(float2*)(c0p + d) = oA;
        float2 gB = *(const float2*)(g1p + d);
        float2 oB;
        oB.x = o_[nt][2] * inv1 * (1.f / (1.f + __expf(-gB.x)));
        oB.y = o_[nt][3] * inv1 * (1.f / (1.f + __expf(-gB.y)));
        *(float2*)(c1p + d) = oB;
    }
}

// -----------------------------------------------------------------------------
extern "C" void kernel_launch(void* const* d_in, const int* in_sizes, int n_in,
                              void* d_out, int out_size)
{
    const float* hidden = (const float*)d_in[0];
    const float* rope   = (const float*)d_in[1];
    const float* Wq     = (const float*)d_in[2];
    const float* bq     = (const float*)d_in[3];
    const float* Wk     = (const float*)d_in[4];
    const float* bk     = (const float*)d_in[5];
    const float* Wv     = (const float*)d_in[6];
    const float* bv     = (const float*)d_in[7];
    const float* Wo     = (const float*)d_in[8];
    const float* bo     = (const float*)d_in[9];
    const float* qw     = (const float*)d_in[10];
    const float* kw     = (const float*)d_in[11];
    float* out = (float*)d_out;

    float *qkv, *ctx;
    cudaGetSymbolAddress((void**)&qkv, g_qkv);
    cudaGetSymbolAddress((void**)&ctx, g_ctx);

    cudaFuncSetAttribute((const void*)attn_kernel,
                         cudaFuncAttributeMaxDynamicSharedMemorySize,
                         ATT_SMEM_BYTES);

    dim3 blk(256);
    gemm_bf16x3<<<dim3(16, 64), blk>>>(hidden, Wq, bq, qkv, 2048, 1024, 2560, 0);
    gemm_bf16x3<<<dim3(2, 64),  blk>>>(hidden, Wk, bk, qkv,  256, 1024, 2560, 2048);
    gemm_bf16x3<<<dim3(2, 64),  blk>>>(hidden, Wv, bv, qkv,  256, 1024, 2560, 2304);

    transform_kernel<<<M_ROWS, 384>>>(qkv, rope, qw, kw);

    attn_kernel<<<dim3(16, NH, NB), 256, ATT_SMEM_BYTES>>>();

    gemm_bf16x3<<<dim3(8, 64), blk>>>(ctx, Wo, bo, out, 1024, 1024, 1024, 0);
}

// round 5
// speedup vs baseline: 2.8074x; 1.1179x over previous
#include <cuda_runtime.h>
#include <math.h>

// Problem constants: B=4, S=2048, HID=1024, H=8, KV=2, HD=128, G=4
#define M_ROWS   8192
#define S_LEN    2048
#define NB       4
#define NH       8
#define NKV      2
#define HD       128

// ---------------- scratch ----------------------------------------------------
__device__ float g_qkv [(size_t)M_ROWS * 2560];
__device__ float g_q   [(size_t)NB * NH  * S_LEN * HD];
__device__ float g_k   [(size_t)NB * NKV * S_LEN * HD];
__device__ float g_v   [(size_t)NB * NKV * S_LEN * HD];
__device__ float g_gate[(size_t)NB * S_LEN * NH * HD];
__device__ float g_ctx [(size_t)M_ROWS * 1024];

// ---------------- bf16 split helpers ------------------------------------------
__device__ __forceinline__ void split_pair(float x0, float x1,
                                           unsigned& hi, unsigned& lo) {
    unsigned h;
    asm("cvt.rn.bf16x2.f32 %0, %1, %2;" : "=r"(h) : "f"(x1), "f"(x0));
    float r0 = x0 - __uint_as_float(h << 16);
    float r1 = x1 - __uint_as_float(h & 0xffff0000u);
    unsigned l;
    asm("cvt.rn.bf16x2.f32 %0, %1, %2;" : "=r"(l) : "f"(r1), "f"(r0));
    hi = h; lo = l;
}

__device__ __forceinline__ void mma_bf16(float* d, const unsigned* a,
                                         const unsigned* b, const float* c) {
    asm volatile(
        "mma.sync.aligned.m16n8k16.row.col.f32.bf16.bf16.f32 "
        "{%0,%1,%2,%3}, {%4,%5,%6,%7}, {%8,%9}, {%10,%11,%12,%13};\n"
        : "=f"(d[0]), "=f"(d[1]), "=f"(d[2]), "=f"(d[3])
        : "r"(a[0]), "r"(a[1]), "r"(a[2]), "r"(a[3]),
          "r"(b[0]), "r"(b[1]),
          "f"(c[0]), "f"(c[1]), "f"(c[2]), "f"(c[3]));
}

__device__ __forceinline__ void ldsm_x4(unsigned* r, unsigned addr) {
    asm volatile("ldmatrix.sync.aligned.m8n8.x4.shared.b16 {%0,%1,%2,%3}, [%4];"
                 : "=r"(r[0]), "=r"(r[1]), "=r"(r[2]), "=r"(r[3]) : "r"(addr));
}
__device__ __forceinline__ void ldsm_x2(unsigned* r, unsigned addr) {
    asm volatile("ldmatrix.sync.aligned.m8n8.x2.shared.b16 {%0,%1}, [%2];"
                 : "=r"(r[0]), "=r"(r[1]) : "r"(addr));
}
__device__ __forceinline__ void ldsm_x2t(unsigned* r, unsigned addr) {
    asm volatile("ldmatrix.sync.aligned.m8n8.x2.trans.shared.b16 {%0,%1}, [%2];"
                 : "=r"(r[0]), "=r"(r[1]) : "r"(addr));
}

__device__ __forceinline__ void cp16(unsigned dst, const void* src) {
    asm volatile("cp.async.cg.shared.global [%0], [%1], 16;\n"
                 :: "r"(dst), "l"(src));
}
#define CP_COMMIT()  asm volatile("cp.async.commit_group;\n")
#define CP_WAIT(n)   asm volatile("cp.async.wait_group %0;\n" :: "n"(n))

// -----------------------------------------------------------------------------
// 3xBF16 GEMM: unchanged from round 4.
// -----------------------------------------------------------------------------
#define AP_W 2560   // 128 rows * pitch 20
#define BP_W 2112   // 16 pair-rows * pitch 132

__global__ __launch_bounds__(256, 1) void gemm_bf16x3(
    const float* __restrict__ A, const float* __restrict__ Bm,
    const float* __restrict__ bias, float* __restrict__ C,
    int N, int K, int ldc, int ccol0)
{
    __shared__ unsigned Ah[AP_W], Al[AP_W], Bh[BP_W], Bl[BP_W];

    const int t    = threadIdx.x;
    const int warp = t >> 5;
    const int lane = t & 31;
    const int wm   = warp >> 2;
    const int wn   = warp & 3;
    const int m0   = blockIdx.y * 128;
    const int n0   = blockIdx.x * 128;
    const int g    = lane >> 2;
    const int c    = lane & 3;

    float acc[4][4][4];
#pragma unroll
    for (int mt = 0; mt < 4; mt++)
#pragma unroll
        for (int nt = 0; nt < 4; nt++)
#pragma unroll
            for (int i = 0; i < 4; i++) acc[mt][nt][i] = 0.f;

    float4 ra[4], rb0[2], rb1[2];
#pragma unroll
    for (int l = 0; l < 4; l++) {
        int idx = t + l * 256;
        ra[l] = *(const float4*)(A + (size_t)(m0 + (idx >> 3)) * K + 4 * (idx & 7));
    }
#pragma unroll
    for (int l = 0; l < 2; l++) {
        int idx = t + l * 256;
        int pr = idx >> 5, cb = 4 * (idx & 31);
        rb0[l] = *(const float4*)(Bm + (size_t)(2 * pr)     * N + n0 + cb);
        rb1[l] = *(const float4*)(Bm + (size_t)(2 * pr + 1) * N + n0 + cb);
    }

    for (int k0 = 0; k0 < K; k0 += 32) {
#pragma unroll
        for (int l = 0; l < 4; l++) {
            int idx = t + l * 256;
            int o = (idx >> 3) * 20 + 2 * (idx & 7);
            split_pair(ra[l].x, ra[l].y, Ah[o],     Al[o]);
            split_pair(ra[l].z, ra[l].w, Ah[o + 1], Al[o + 1]);
        }
#pragma unroll
        for (int l = 0; l < 2; l++) {
            int idx = t + l * 256;
            int o = (idx >> 5) * 132 + 4 * (idx & 31);
            split_pair(rb0[l].x, rb1[l].x, Bh[o],     Bl[o]);
            split_pair(rb0[l].y, rb1[l].y, Bh[o + 1], Bl[o + 1]);
            split_pair(rb0[l].z, rb1[l].z, Bh[o + 2], Bl[o + 2]);
            split_pair(rb0[l].w, rb1[l].w, Bh[o + 3], Bl[o + 3]);
        }
        __syncthreads();

        if (k0 + 32 < K) {
            int kn = k0 + 32;
#pragma unroll
            for (int l = 0; l < 4; l++) {
                int idx = t + l * 256;
                ra[l] = *(const float4*)(A + (size_t)(m0 + (idx >> 3)) * K + kn + 4 * (idx & 7));
            }
#pragma unroll
            for (int l = 0; l < 2; l++) {
                int idx = t + l * 256;
                int pr = idx >> 5, cb = 4 * (idx & 31);
                rb0[l] = *(const float4*)(Bm + (size_t)(kn + 2 * pr)     * N + n0 + cb);
                rb1[l] = *(const float4*)(Bm + (size_t)(kn + 2 * pr + 1) * N + n0 + cb);
            }
        }

#pragma unroll
        for (int ks = 0; ks < 2; ks++) {
            unsigned afh[4][4], afl[4][4];
#pragma unroll
            for (int mt = 0; mt < 4; mt++) {
                int rw = (wm * 64 + mt * 16 + g) * 20 + ks * 8;
                afh[mt][0] = Ah[rw + c];       afh[mt][1] = Ah[rw + 160 + c];
                afh[mt][2] = Ah[rw + c + 4];   afh[mt][3] = Ah[rw + 160 + c + 4];
                afl[mt][0] = Al[rw + c];       afl[mt][1] = Al[rw + 160 + c];
                afl[mt][2] = Al[rw + c + 4];   afl[mt][3] = Al[rw + 160 + c + 4];
            }
            unsigned bfh[4][2], bfl[4][2];
#pragma unroll
            for (int nt = 0; nt < 4; nt++) {
                int col = wn * 32 + nt * 8 + g;
                bfh[nt][0] = Bh[(ks * 8 + c) * 132 + col];
                bfh[nt][1] = Bh[(ks * 8 + c + 4) * 132 + col];
                bfl[nt][0] = Bl[(ks * 8 + c) * 132 + col];
                bfl[nt][1] = Bl[(ks * 8 + c + 4) * 132 + col];
            }
#pragma unroll
            for (int nt = 0; nt < 4; nt++)
#pragma unroll
                for (int mt = 0; mt < 4; mt++)
                    mma_bf16(acc[mt][nt], afh[mt], bfh[nt], acc[mt][nt]);
#pragma unroll
            for (int nt = 0; nt < 4; nt++)
#pragma unroll
                for (int mt = 0; mt < 4; mt++)
                    mma_bf16(acc[mt][nt], afh[mt], bfl[nt], acc[mt][nt]);
#pragma unroll
            for (int nt = 0; nt < 4; nt++)
#pragma unroll
                for (int mt = 0; mt < 4; mt++)
                    mma_bf16(acc[mt][nt], afl[mt], bfh[nt], acc[mt][nt]);
        }
        __syncthreads();
    }

#pragma unroll
    for (int mt = 0; mt < 4; mt++) {
        int row = m0 + wm * 64 + mt * 16 + g;
#pragma unroll
        for (int nt = 0; nt < 4; nt++) {
            int col = n0 + wn * 32 + nt * 8 + 2 * c;
            float bx = bias[col], by = bias[col + 1];
            float2 o0 = make_float2(acc[mt][nt][0] + bx, acc[mt][nt][1] + by);
            float2 o1 = make_float2(acc[mt][nt][2] + bx, acc[mt][nt][3] + by);
            *(float2*)(C + (size_t)row * ldc + ccol0 + col)       = o0;
            *(float2*)(C + (size_t)(row + 8) * ldc + ccol0 + col) = o1;
        }
    }
}

// -----------------------------------------------------------------------------
// Transform: RMSNorm + RoPE on Q/K heads, copy V and gate. (unchanged)
// -----------------------------------------------------------------------------
__global__ __launch_bounds__(384) void transform_kernel(
    const float* __restrict__ qkv, const float* __restrict__ rope,
    const float* __restrict__ qw,  const float* __restrict__ kw)
{
    const int bs = blockIdx.x;
    const int b  = bs >> 11;
    const int s  = bs & 2047;
    const float* row = qkv + (size_t)bs * 2560;
    const float* emb = rope + (size_t)s * 256;
    const int w    = threadIdx.x >> 5;
    const int lane = threadIdx.x & 31;

    if (w < 10) {
        const bool isq = (w < 8);
        int off, outbase;
        const float* nw;
        if (isq) {
            int kvh = w >> 2;
            off     = kvh * 1024 + (w & 3) * 128;
            nw      = qw;
            outbase = ((b * NH + w) * S_LEN + s) * HD;
        } else {
            int j   = w - 8;
            off     = 2048 + j * 128;
            nw      = kw;
            outbase = ((b * NKV + j) * S_LEN + s) * HD;
        }
        const int d = lane * 4;
        float4 x = *(const float4*)(row + off + d);
        float ss = x.x * x.x + x.y * x.y + x.z * x.z + x.w * x.w;
#pragma unroll
        for (int o = 16; o > 0; o >>= 1) ss += __shfl_xor_sync(0xffffffffu, ss, o);
        float rn = rsqrtf(ss * (1.0f / 128.0f) + 1e-6f);
        float4 wv = *(const float4*)(nw + d);
        x.x *= rn * wv.x; x.y *= rn * wv.y; x.z *= rn * wv.z; x.w *= rn * wv.w;
        float4 sn = *(const float4*)(emb + d);
        float4 cs = *(const float4*)(emb + 128 + d);
        float4 y;
        y.x = x.x * cs.x - x.y * sn.x;
        y.y = x.y * cs.y + x.x * sn.y;
        y.z = x.z * cs.z - x.w * sn.z;
        y.w = x.w * cs.w + x.z * sn.w;
        float* dst = (isq ? g_q : g_k) + outbase + d;
        *(float4*)dst = y;
    } else if (w == 10) {
#pragma unroll
        for (int rr = 0; rr < 2; rr++) {
            int f = lane + rr * 32;
            int j = f >> 5, cc = f & 31;
            float4 v = *(const float4*)(row + 2304 + j * 128 + cc * 4);
            *(float4*)(g_v + ((size_t)((b * NKV + j) * S_LEN + s)) * HD + cc * 4) = v;
        }
    } else {
#pragma unroll
        for (int rr = 0; rr < 8; rr++) {
            int f  = lane + rr * 32;
            int hh = f >> 5, cc = f & 31;
            int src = (hh >> 2) * 1024 + 512 + (hh & 3) * 128 + cc * 4;
            float4 v = *(const float4*)(row + src);
            *(float4*)(g_gate + ((size_t)(bs * NH + hh)) * HD + cc * 4) = v;
        }
    }
}

// -----------------------------------------------------------------------------
// Flash attention v3: 3xBF16, K-tile 64, cp.async raw staging, ldmatrix frags.
// Block: 128 queries x one (b,h). 8 warps x 16 q-rows.
// smem (words):
//   Qh[128][68]  @0       Ql[128][68]  @8704
//   Kh[64][68]   @17408   Kl[64][68]   @21760   (key-major, packed dim pairs)
//   Vh[64][68]   @26112   Vl[64][68]   @30464   (key-major; LDSM.trans for PV)
//   RawK[64][128]@34816   RawV[64][128]@43008   (fp32 cp.async staging)
// -----------------------------------------------------------------------------
#define QH_OFF   0
#define QL_OFF   8704
#define KH_OFF   17408
#define KL_OFF   21760
#define VH_OFF   26112
#define VL_OFF   30464
#define RAWK_OFF 34816
#define RAWV_OFF 43008
#define ATT_WORDS 51200
#define ATT_SMEM_BYTES (ATT_WORDS * 4)

__global__ __launch_bounds__(256, 1) void attn_kernel()
{
    extern __shared__ __align__(16) unsigned sm[];
    const unsigned smb = (unsigned)__cvta_generic_to_shared(sm);

    const int t    = threadIdx.x;
    const int warp = t >> 5;
    const int lane = t & 31;
    const int g    = lane >> 2;
    const int c    = lane & 3;
    const int b    = blockIdx.z;
    const int h    = blockIdx.y;
    const int q0   = blockIdx.x * 128;
    const int kv   = h >> 2;
    const float scale = 0.08838834764831845f;

    const float* Qg = g_q + ((size_t)((b * NH + h) * S_LEN + q0)) * HD;
    const float* Kb = g_k + ((size_t)(b * NKV + kv)) * S_LEN * HD;
    const float* Vb = g_v + ((size_t)(b * NKV + kv)) * S_LEN * HD;

    // cp.async issue of one raw K/V tile (64 keys x 128 dims fp32)
    auto issue = [&](int kt) {
        const float* Kt = Kb + (size_t)kt * 64 * 128;
        const float* Vt = Vb + (size_t)kt * 64 * 128;
#pragma unroll
        for (int i = 0; i < 8; i++) {
            int r = (t >> 5) + 8 * i;           // 0..63
            unsigned off = (r * 128 + 4 * lane) * 4;
            cp16(smb + RAWK_OFF * 4 + off, Kt + r * 128 + 4 * lane);
            cp16(smb + RAWV_OFF * 4 + off, Vt + r * 128 + 4 * lane);
        }
    };

    issue(0);
    CP_COMMIT();

    // Q load: scale + split into packed bf16x2 (overlaps cp.async)
    unsigned* Qh = sm + QH_OFF;
    unsigned* Ql = sm + QL_OFF;
#pragma unroll
    for (int i = 0; i < 16; i++) {
        int r = (t >> 5) + 8 * i;               // 0..127
        float4 v = *(const float4*)(Qg + (size_t)r * 128 + 4 * lane);
        int o = r * 68 + 2 * lane;
        split_pair(v.x * scale, v.y * scale, Qh[o],     Ql[o]);
        split_pair(v.z * scale, v.w * scale, Qh[o + 1], Ql[o + 1]);
    }

    // ldmatrix lane base addresses (bytes)
    const unsigned qah = smb + ((QH_OFF + (warp * 16 + (lane & 15)) * 68 + (lane >> 4) * 4) * 4);
    const unsigned qal = qah + (QL_OFF - QH_OFF) * 4;
    const unsigned kha = smb + ((KH_OFF + (lane & 7) * 68 + ((lane >> 3) & 1) * 4) * 4);
    const unsigned kla = kha + (KL_OFF - KH_OFF) * 4;
    const unsigned vha = smb + ((VH_OFF + (lane & 15) * 68) * 4);
    const unsigned vla = vha + (VL_OFF - VH_OFF) * 4;

    float o_[16][4];
#pragma unroll
    for (int nt = 0; nt < 16; nt++)
#pragma unroll
        for (int i = 0; i < 4; i++) o_[nt][i] = 0.f;
    float m0 = -1e30f, m1 = -1e30f, sl0 = 0.f, sl1 = 0.f;

    for (int kt = 0; kt < 32; kt++) {
        CP_WAIT(0);
        __syncthreads();   // raw ready; previous compute done with split tiles

        // ---- split raw fp32 -> packed bf16x2 hi/lo tiles (key-major) ----
        {
            const float* RK = (const float*)(sm + RAWK_OFF);
            const float* RV = (const float*)(sm + RAWV_OFF);
            unsigned* Kh = sm + KH_OFF; unsigned* Kl = sm + KL_OFF;
            unsigned* Vh = sm + VH_OFF; unsigned* Vl = sm + VL_OFF;
#pragma unroll
            for (int i = 0; i < 8; i++) {
                int r = (t >> 5) + 8 * i;        // 0..63
                int o = r * 68 + 2 * lane;
                float4 kk = *(const float4*)(RK + r * 128 + 4 * lane);
                unsigned h0, e0, h1, e1;
                split_pair(kk.x, kk.y, h0, e0);
                split_pair(kk.z, kk.w, h1, e1);
                *(uint2*)(Kh + o) = make_uint2(h0, h1);
                *(uint2*)(Kl + o) = make_uint2(e0, e1);
                float4 vv = *(const float4*)(RV + r * 128 + 4 * lane);
                split_pair(vv.x, vv.y, h0, e0);
                split_pair(vv.z, vv.w, h1, e1);
                *(uint2*)(Vh + o) = make_uint2(h0, h1);
                *(uint2*)(Vl + o) = make_uint2(e0, e1);
            }
        }
        __syncthreads();   // split tiles ready; raw free for next cp.async

        if (kt < 31) { issue(kt + 1); CP_COMMIT(); }

        // ---- scores S = Q K^T : warp does 16 q-rows x 64 keys ----
        float sc[8][4];
#pragma unroll
        for (int nt = 0; nt < 8; nt++)
#pragma unroll
            for (int i = 0; i < 4; i++) sc[nt][i] = 0.f;

#pragma unroll
        for (int ks = 0; ks < 8; ks++) {
            unsigned ah[4], al[4];
            ldsm_x4(ah, qah + ks * 32);
            ldsm_x4(al, qal + ks * 32);
#pragma unroll
            for (int nt = 0; nt < 8; nt++) {
                unsigned bh[2], bl[2];
                unsigned off = (nt * 8 * 68 + ks * 8) * 4;
                ldsm_x2(bh, kha + off);
                ldsm_x2(bl, kla + off);
                mma_bf16(sc[nt], ah, bh, sc[nt]);
                mma_bf16(sc[nt], ah, bl, sc[nt]);
                mma_bf16(sc[nt], al, bh, sc[nt]);
            }
        }

        // ---- online softmax (rows g, g+8) ----
        float t0 = -1e30f, t1 = -1e30f;
#pragma unroll
        for (int nt = 0; nt < 8; nt++) {
            t0 = fmaxf(t0, fmaxf(sc[nt][0], sc[nt][1]));
            t1 = fmaxf(t1, fmaxf(sc[nt][2], sc[nt][3]));
        }
        t0 = fmaxf(t0, __shfl_xor_sync(0xffffffffu, t0, 1));
        t0 = fmaxf(t0, __shfl_xor_sync(0xffffffffu, t0, 2));
        t1 = fmaxf(t1, __shfl_xor_sync(0xffffffffu, t1, 1));
        t1 = fmaxf(t1, __shfl_xor_sync(0xffffffffu, t1, 2));
        float mn0 = fmaxf(m0, t0), mn1 = fmaxf(m1, t1);
        float al0 = __expf(m0 - mn0), al1 = __expf(m1 - mn1);
        m0 = mn0; m1 = mn1;
        float s0 = 0.f, s1 = 0.f;
#pragma unroll
        for (int nt = 0; nt < 8; nt++) {
            sc[nt][0] = __expf(sc[nt][0] - mn0); s0 += sc[nt][0];
            sc[nt][1] = __expf(sc[nt][1] - mn0); s0 += sc[nt][1];
            sc[nt][2] = __expf(sc[nt][2] - mn1); s1 += sc[nt][2];
            sc[nt][3] = __expf(sc[nt][3] - mn1); s1 += sc[nt][3];
        }
        s0 += __shfl_xor_sync(0xffffffffu, s0, 1);
        s0 += __shfl_xor_sync(0xffffffffu, s0, 2);
        s1 += __shfl_xor_sync(0xffffffffu, s1, 1);
        s1 += __shfl_xor_sync(0xffffffffu, s1, 2);
        sl0 = sl0 * al0 + s0;
        sl1 = sl1 * al1 + s1;
#pragma unroll
        for (int nt = 0; nt < 16; nt++) {
            o_[nt][0] *= al0; o_[nt][1] *= al0;
            o_[nt][2] *= al1; o_[nt][3] *= al1;
        }

        // ---- O += P V : P C-frag is the k16 A-frag; V via LDSM.trans ----
#pragma unroll
        for (int ks = 0; ks < 4; ks++) {
            unsigned ah[4], al[4];
            split_pair(sc[2 * ks][0],     sc[2 * ks][1],     ah[0], al[0]);
            split_pair(sc[2 * ks][2],     sc[2 * ks][3],     ah[1], al[1]);
            split_pair(sc[2 * ks + 1][0], sc[2 * ks + 1][1], ah[2], al[2]);
            split_pair(sc[2 * ks + 1][2], sc[2 * ks + 1][3], ah[3], al[3]);
#pragma unroll
            for (int nt = 0; nt < 16; nt++) {
                unsigned bh[2], bl[2];
                unsigned off = (ks * 16 * 68 + nt * 4) * 4;
                ldsm_x2t(bh, vha + off);
                ldsm_x2t(bl, vla + off);
                mma_bf16(o_[nt], ah, bh, o_[nt]);
                mma_bf16(o_[nt], ah, bl, o_[nt]);
                mma_bf16(o_[nt], al, bh, o_[nt]);
            }
        }
    }

    // ---- epilogue: normalize, sigmoid-gate, store ----
    float inv0 = 1.f / sl0, inv1 = 1.f / sl1;
    int qrow0 = q0 + warp * 16 + g;
    int qrow1 = qrow0 + 8;
    const float* g0p = g_gate + ((size_t)((b * S_LEN + qrow0) * NH + h)) * HD;
    const float* g1p = g_gate + ((size_t)((b * S_LEN + qrow1) * NH + h)) * HD;
    float* c0p = g_ctx + (size_t)(b * S_LEN + qrow0) * 1024 + h * HD;
    float* c1p = g_ctx + (size_t)(b * S_LEN + qrow1) * 1024 + h * HD;
#pragma unroll
    for (int nt = 0; nt < 16; nt++) {
        int d = nt * 8 + 2 * c;
        float2 gA = *(const float2*)(g0p + d);
        float2 oA;
        oA.x = o_[nt][0] * inv0 * (1.f / (1.f + __expf(-gA.x)));
        oA.y = o_[nt][1] * inv0 * (1.f / (1.f + __expf(-gA.y)));
        *(float2*)(c0p + d) = oA;
        float2 gB = *(const float2*)(g1p + d);
        float2 oB;
        oB.x = o_[nt][2] * inv1 * (1.f / (1.f + __expf(-gB.x)));
        oB.y = o_[nt][3] * inv1 * (1.f / (1.f + __expf(-gB.y)));
        *(float2*)(c1p + d) = oB;
    }
}

// -----------------------------------------------------------------------------
extern "C" void kernel_launch(void* const* d_in, const int* in_sizes, int n_in,
                              void* d_out, int out_size)
{
    const float* hidden = (const float*)d_in[0];
    const float* rope   = (const float*)d_in[1];
    const float* Wq     = (const float*)d_in[2];
    const float* bq     = (const float*)d_in[3];
    const float* Wk     = (const float*)d_in[4];
    const float* bk     = (const float*)d_in[5];
    const float* Wv     = (const float*)d_in[6];
    const float* bv     = (const float*)d_in[7];
    const float* Wo     = (const float*)d_in[8];
    const float* bo     = (const float*)d_in[9];
    const float* qw     = (const float*)d_in[10];
    const float* kw     = (const float*)d_in[11];
    float* out = (float*)d_out;

    float *qkv, *ctx;
    cudaGetSymbolAddress((void**)&qkv, g_qkv);
    cudaGetSymbolAddress((void**)&ctx, g_ctx);

    cudaFuncSetAttribute((const void*)attn_kernel,
                         cudaFuncAttributeMaxDynamicSharedMemorySize,
                         ATT_SMEM_BYTES);

    dim3 blk(256);
    gemm_bf16x3<<<dim3(16, 64), blk>>>(hidden, Wq, bq, qkv, 2048, 1024, 2560, 0);
    gemm_bf16x3<<<dim3(2, 64),  blk>>>(hidden, Wk, bk, qkv,  256, 1024, 2560, 2048);
    gemm_bf16x3<<<dim3(2, 64),  blk>>>(hidden, Wv, bv, qkv,  256, 1024, 2560, 2304);

    transform_kernel<<<M_ROWS, 384>>>(qkv, rope, qw, kw);

    attn_kernel<<<dim3(16, NH, NB), 256, ATT_SMEM_BYTES>>>();

    gemm_bf16x3<<<dim3(8, 64), blk>>>(ctx, Wo, bo, out, 1024, 1024, 1024, 0);
}

// round 6
// speedup vs baseline: 3.1708x; 1.1294x over previous
#include <cuda_runtime.h>
#include <math.h>

// Problem constants: B=4, S=2048, HID=1024, H=8, KV=2, HD=128, G=4
#define M_ROWS   8192
#define S_LEN    2048
#define NB       4
#define NH       8
#define NKV      2
#define HD       128

// ---------------- persistent split scratch (bf16 packed in unsigned words) ----
__device__ unsigned g_hidh[(size_t)M_ROWS * 512], g_hidl[(size_t)M_ROWS * 512];
__device__ unsigned g_wqkvh[(size_t)1024 * 1280], g_wqkvl[(size_t)1024 * 1280];
__device__ unsigned g_woh[(size_t)1024 * 512],  g_wol[(size_t)1024 * 512];
__device__ unsigned g_qh[(size_t)NB * NH * S_LEN * 64],  g_ql[(size_t)NB * NH * S_LEN * 64];
__device__ unsigned g_kh[(size_t)NB * NKV * S_LEN * 64], g_kl[(size_t)NB * NKV * S_LEN * 64];
__device__ unsigned g_vh[(size_t)NB * NKV * S_LEN * 64], g_vl[(size_t)NB * NKV * S_LEN * 64];
__device__ unsigned g_ctxh[(size_t)M_ROWS * 512], g_ctxl[(size_t)M_ROWS * 512];
__device__ float    g_qkv[(size_t)M_ROWS * 2560];
__device__ float    g_gate[(size_t)NB * S_LEN * NH * HD];
__device__ float    g_biasqkv[2560];

// ---------------- helpers ------------------------------------------------------
__device__ __forceinline__ void split_pair(float x0, float x1,
                                           unsigned& hi, unsigned& lo) {
    unsigned h;
    asm("cvt.rn.bf16x2.f32 %0, %1, %2;" : "=r"(h) : "f"(x1), "f"(x0));
    float r0 = x0 - __uint_as_float(h << 16);
    float r1 = x1 - __uint_as_float(h & 0xffff0000u);
    unsigned l;
    asm("cvt.rn.bf16x2.f32 %0, %1, %2;" : "=r"(l) : "f"(r1), "f"(r0));
    hi = h; lo = l;
}

__device__ __forceinline__ void mma_bf16(float* d, const unsigned* a,
                                         const unsigned* b, const float* c) {
    asm volatile(
        "mma.sync.aligned.m16n8k16.row.col.f32.bf16.bf16.f32 "
        "{%0,%1,%2,%3}, {%4,%5,%6,%7}, {%8,%9}, {%10,%11,%12,%13};\n"
        : "=f"(d[0]), "=f"(d[1]), "=f"(d[2]), "=f"(d[3])
        : "r"(a[0]), "r"(a[1]), "r"(a[2]), "r"(a[3]),
          "r"(b[0]), "r"(b[1]),
          "f"(c[0]), "f"(c[1]), "f"(c[2]), "f"(c[3]));
}

__device__ __forceinline__ void ldsm_x4(unsigned* r, unsigned addr) {
    asm volatile("ldmatrix.sync.aligned.m8n8.x4.shared.b16 {%0,%1,%2,%3}, [%4];"
                 : "=r"(r[0]), "=r"(r[1]), "=r"(r[2]), "=r"(r[3]) : "r"(addr));
}
__device__ __forceinline__ void ldsm_x4t(unsigned* r, unsigned addr) {
    asm volatile("ldmatrix.sync.aligned.m8n8.x4.trans.shared.b16 {%0,%1,%2,%3}, [%4];"
                 : "=r"(r[0]), "=r"(r[1]), "=r"(r[2]), "=r"(r[3]) : "r"(addr));
}

__device__ __forceinline__ void cp16(unsigned dst, const void* src) {
    asm volatile("cp.async.cg.shared.global [%0], [%1], 16;\n"
                 :: "r"(dst), "l"(src));
}
#define CP_COMMIT()  asm volatile("cp.async.commit_group;\n")
#define CP_WAIT0()   asm volatile("cp.async.wait_group 0;\n")

// ---------------- one-shot split kernels ---------------------------------------
__global__ __launch_bounds__(256) void split2d(
    const float* __restrict__ src, unsigned* __restrict__ hi,
    unsigned* __restrict__ lo, int cols4, int pitchw, int offw)
{
    int i = blockIdx.x * 256 + threadIdx.x;
    int row = i / cols4, c4 = i - row * cols4;
    float4 v = *(const float4*)(src + ((size_t)row * cols4 + c4) * 4);
    unsigned h0, l0, h1, l1;
    split_pair(v.x, v.y, h0, l0);
    split_pair(v.z, v.w, h1, l1);
    size_t o = (size_t)row * pitchw + offw + c4 * 2;
    *(uint2*)(hi + o) = make_uint2(h0, h1);
    *(uint2*)(lo + o) = make_uint2(l0, l1);
}

__global__ __launch_bounds__(256) void concat_bias(
    const float* __restrict__ bq, const float* __restrict__ bk,
    const float* __restrict__ bv)
{
    int i = blockIdx.x * 256 + threadIdx.x;
    float v;
    if (i < 2048)      v = bq[i];
    else if (i < 2304) v = bk[i - 2048];
    else               v = bv[i - 2304];
    g_biasqkv[i] = v;
}

// -----------------------------------------------------------------------------
// 3xBF16 GEMM on pre-split inputs. C = A(8192xK=1024) @ B(KxN) + bias.
// Block 128x128, kstep 32, 8 warps (2m x 4n). cp.async double-buffered.
// stage words: Ah[128][20]=2560 | Al 2560 | Bh[32][68]=2176 | Bl 2176 = 9472
// -----------------------------------------------------------------------------
#define G_STAGE 9472
#define GEMM_SMEM_BYTES (2 * G_STAGE * 4)

__global__ __launch_bounds__(256, 1) void gemm_bf16s(
    const unsigned* __restrict__ Ahg, const unsigned* __restrict__ Alg,
    const unsigned* __restrict__ Bhg, const unsigned* __restrict__ Blg,
    const float* __restrict__ bias, float* __restrict__ C,
    int Nw, int ldc)
{
    extern __shared__ __align__(16) unsigned gsm[];
    const unsigned smb = (unsigned)__cvta_generic_to_shared(gsm);

    const int t    = threadIdx.x;
    const int warp = t >> 5;
    const int lane = t & 31;
    const int wm   = warp >> 2;
    const int wn   = warp & 3;
    const int m0   = blockIdx.y * 128;
    const int n0   = blockIdx.x * 128;
    const int g    = lane >> 2;
    const int c    = lane & 3;
    const int nw0  = n0 >> 1;

    auto issue = [&](int k0, int buf) {
        unsigned base = smb + buf * G_STAGE * 4;
#pragma unroll
        for (int l = 0; l < 2; l++) {
            int ci = t + l * 256;
            int row = ci >> 2, cc = ci & 3;
            size_t srcw = (size_t)(m0 + row) * 512 + (k0 >> 1) + cc * 4;
            unsigned dst = base + (row * 20 + cc * 4) * 4;
            cp16(dst,             Ahg + srcw);
            cp16(dst + 2560 * 4,  Alg + srcw);
        }
#pragma unroll
        for (int l = 0; l < 2; l++) {
            int ci = t + l * 256;
            int row = ci >> 4, cc = ci & 15;
            size_t srcw = (size_t)(k0 + row) * Nw + nw0 + cc * 4;
            unsigned dst = base + (5120 + row * 68 + cc * 4) * 4;
            cp16(dst,             Bhg + srcw);
            cp16(dst + 2176 * 4,  Blg + srcw);
        }
    };

    issue(0, 0);
    CP_COMMIT();

    float acc[4][4][4];
#pragma unroll
    for (int mt = 0; mt < 4; mt++)
#pragma unroll
        for (int nt = 0; nt < 4; nt++)
#pragma unroll
            for (int i = 0; i < 4; i++) acc[mt][nt][i] = 0.f;

    // fragment base byte offsets (within stage)
    const unsigned gah = ((wm * 64 + (lane & 15)) * 20 + ((lane >> 4) << 2)) * 4;
    const unsigned gbb = 5120 * 4 +
        (((((lane >> 3) & 1) << 3) + (lane & 7)) * 68 + wn * 16 + ((lane >> 4) << 2)) * 4;

    for (int k0 = 0; k0 < 1024; k0 += 32) {
        CP_WAIT0();
        __syncthreads();
        if (k0 + 32 < 1024) { issue(k0 + 32, ((k0 >> 5) + 1) & 1); CP_COMMIT(); }

        const unsigned sb = smb + ((k0 >> 5) & 1) * G_STAGE * 4;
#pragma unroll
        for (int ks = 0; ks < 2; ks++) {
            unsigned ah[4][4], al[4][4];
#pragma unroll
            for (int mt = 0; mt < 4; mt++) {
                ldsm_x4(ah[mt], sb + gah + mt * 1280 + ks * 32);
                ldsm_x4(al[mt], sb + 10240 + gah + mt * 1280 + ks * 32);
            }
#pragma unroll
            for (int np = 0; np < 2; np++) {
                unsigned bh4[4], bl4[4];
                unsigned boff = sb + gbb + ks * 4352 + np * 32;
                ldsm_x4t(bh4, boff);
                ldsm_x4t(bl4, boff + 2176 * 4);
#pragma unroll
                for (int mt = 0; mt < 4; mt++) {
                    mma_bf16(acc[mt][2 * np],     ah[mt], bh4,     acc[mt][2 * np]);
                    mma_bf16(acc[mt][2 * np],     ah[mt], bl4,     acc[mt][2 * np]);
                    mma_bf16(acc[mt][2 * np],     al[mt], bh4,     acc[mt][2 * np]);
                    mma_bf16(acc[mt][2 * np + 1], ah[mt], bh4 + 2, acc[mt][2 * np + 1]);
                    mma_bf16(acc[mt][2 * np + 1], ah[mt], bl4 + 2, acc[mt][2 * np + 1]);
                    mma_bf16(acc[mt][2 * np + 1], al[mt], bh4 + 2, acc[mt][2 * np + 1]);
                }
            }
        }
    }

#pragma unroll
    for (int mt = 0; mt < 4; mt++) {
        int row = m0 + wm * 64 + mt * 16 + g;
#pragma unroll
        for (int nt = 0; nt < 4; nt++) {
            int col = n0 + wn * 32 + nt * 8 + 2 * c;
            float bx = bias[col], by = bias[col + 1];
            float2 o0 = make_float2(acc[mt][nt][0] + bx, acc[mt][nt][1] + by);
            float2 o1 = make_float2(acc[mt][nt][2] + bx, acc[mt][nt][3] + by);
            *(float2*)(C + (size_t)row * ldc + col)       = o0;
            *(float2*)(C + (size_t)(row + 8) * ldc + col) = o1;
        }
    }
}

// -----------------------------------------------------------------------------
// Transform: RMSNorm + RoPE; writes SPLIT bf16 Q (pre-scaled)/K/V + fp32 gate.
// -----------------------------------------------------------------------------
__global__ __launch_bounds__(384) void transform_kernel(
    const float* __restrict__ qkv, const float* __restrict__ rope,
    const float* __restrict__ qw,  const float* __restrict__ kw)
{
    const int bs = blockIdx.x;
    const int b  = bs >> 11;
    const int s  = bs & 2047;
    const float* row = qkv + (size_t)bs * 2560;
    const float* emb = rope + (size_t)s * 256;
    const int w    = threadIdx.x >> 5;
    const int lane = threadIdx.x & 31;

    if (w < 10) {
        const bool isq = (w < 8);
        int off;
        size_t outrow;
        const float* nw;
        if (isq) {
            int kvh = w >> 2;
            off    = kvh * 1024 + (w & 3) * 128;
            nw     = qw;
            outrow = ((size_t)(b * NH + w) * S_LEN + s);
        } else {
            int j  = w - 8;
            off    = 2048 + j * 128;
            nw     = kw;
            outrow = ((size_t)(b * NKV + j) * S_LEN + s);
        }
        const int d = lane * 4;
        float4 x = *(const float4*)(row + off + d);
        float ss = x.x * x.x + x.y * x.y + x.z * x.z + x.w * x.w;
#pragma unroll
        for (int o = 16; o > 0; o >>= 1) ss += __shfl_xor_sync(0xffffffffu, ss, o);
        float rn = rsqrtf(ss * (1.0f / 128.0f) + 1e-6f);
        float4 wv = *(const float4*)(nw + d);
        x.x *= rn * wv.x; x.y *= rn * wv.y; x.z *= rn * wv.z; x.w *= rn * wv.w;
        float4 sn = *(const float4*)(emb + d);
        float4 cs = *(const float4*)(emb + 128 + d);
        float4 y;
        y.x = x.x * cs.x - x.y * sn.x;
        y.y = x.y * cs.y + x.x * sn.y;
        y.z = x.z * cs.z - x.w * sn.z;
        y.w = x.w * cs.w + x.z * sn.w;
        float scq = isq ? 0.08838834764831845f : 1.0f;
        unsigned h0, l0, h1, l1;
        split_pair(y.x * scq, y.y * scq, h0, l0);
        split_pair(y.z * scq, y.w * scq, h1, l1);
        unsigned* dh = (isq ? g_qh : g_kh) + outrow * 64 + lane * 2;
        unsigned* dl = (isq ? g_ql : g_kl) + outrow * 64 + lane * 2;
        *(uint2*)dh = make_uint2(h0, h1);
        *(uint2*)dl = make_uint2(l0, l1);
    } else if (w == 10) {
#pragma unroll
        for (int rr = 0; rr < 2; rr++) {
            int f = lane + rr * 32;
            int j = f >> 5, cc = f & 31;
            float4 v = *(const float4*)(row + 2304 + j * 128 + cc * 4);
            unsigned h0, l0, h1, l1;
            split_pair(v.x, v.y, h0, l0);
            split_pair(v.z, v.w, h1, l1);
            size_t o = ((size_t)(b * NKV + j) * S_LEN + s) * 64 + cc * 2;
            *(uint2*)(g_vh + o) = make_uint2(h0, h1);
            *(uint2*)(g_vl + o) = make_uint2(l0, l1);
        }
    } else {
#pragma unroll
        for (int rr = 0; rr < 8; rr++) {
            int f  = lane + rr * 32;
            int hh = f >> 5, cc = f & 31;
            int src = (hh >> 2) * 1024 + 512 + (hh & 3) * 128 + cc * 4;
            float4 v = *(const float4*)(row + src);
            *(float4*)(g_gate + ((size_t)(bs * NH + hh)) * HD + cc * 4) = v;
        }
    }
}

// -----------------------------------------------------------------------------
// Flash attention v4: pre-split bf16 K/V/Q. Pure cp.async -> ldmatrix -> mma.
// Block: 128 q x one (b,h). 8 warps x 16 q-rows. K-tile 64, double-buffered.
// smem words: Qh[128][68]@0 Ql@8704 | stage s@17408+s*17408:
//             Kh[64][68] Kl Vh Vl (4352 each)
// -----------------------------------------------------------------------------
#define AQ_OFF  0
#define AQL_OFF 8704
#define AST_OFF 17408
#define AST_STR 17408
#define ATT_WORDS (17408 + 2 * 17408)
#define ATT_SMEM_BYTES (ATT_WORDS * 4)

__global__ __launch_bounds__(256, 1) void attn_kernel()
{
    extern __shared__ __align__(16) unsigned sm[];
    const unsigned smb = (unsigned)__cvta_generic_to_shared(sm);

    const int t    = threadIdx.x;
    const int warp = t >> 5;
    const int lane = t & 31;
    const int g    = lane >> 2;
    const int c    = lane & 3;
    const int b    = blockIdx.z;
    const int hh   = blockIdx.y;
    const int q0   = blockIdx.x * 128;
    const int kv   = hh >> 2;

    const unsigned* Qgh = g_qh + ((size_t)(b * NH + hh) * S_LEN + q0) * 64;
    const unsigned* Qgl = g_ql + ((size_t)(b * NH + hh) * S_LEN + q0) * 64;
    const size_t kvbase = (size_t)(b * NKV + kv) * S_LEN * 64;

    auto issue_kv = [&](int kt, int buf) {
        unsigned base = smb + (AST_OFF + buf * AST_STR) * 4;
        size_t srow = kvbase + (size_t)kt * 64 * 64;
#pragma unroll
        for (int i = 0; i < 4; i++) {
            int ci = t + i * 256;
            int row = ci >> 4, cc = ci & 15;
            size_t srcw = srow + (size_t)row * 64 + cc * 4;
            unsigned dst = base + (row * 68 + cc * 4) * 4;
            cp16(dst,              g_kh + srcw);
            cp16(dst + 4352 * 4,   g_kl + srcw);
            cp16(dst + 8704 * 4,   g_vh + srcw);
            cp16(dst + 13056 * 4,  g_vl + srcw);
        }
    };

    // Q + first K/V stage in one group
#pragma unroll
    for (int i = 0; i < 8; i++) {
        int ci = t + i * 256;
        int row = ci >> 4, cc = ci & 15;
        size_t srcw = (size_t)row * 64 + cc * 4;
        unsigned dst = smb + (row * 68 + cc * 4) * 4;
        cp16(dst,              Qgh + srcw);
        cp16(dst + 8704 * 4,   Qgl + srcw);
    }
    issue_kv(0, 0);
    CP_COMMIT();

    // fragment base byte offsets
    const unsigned qah = smb + ((warp * 16 + (lane & 15)) * 68 + ((lane >> 4) << 2)) * 4;
    const unsigned qal = qah + 8704 * 4;
    const unsigned kfb = ((((lane >> 4) << 3) + (lane & 7)) * 68 + (((lane >> 3) & 1) << 2)) * 4;
    const unsigned vfb = (((((lane >> 3) & 1) << 3) + (lane & 7)) * 68 + ((lane >> 4) << 2)) * 4;

    float o_[16][4];
#pragma unroll
    for (int nt = 0; nt < 16; nt++)
#pragma unroll
        for (int i = 0; i < 4; i++) o_[nt][i] = 0.f;
    float m0 = -1e30f, m1 = -1e30f, sl0 = 0.f, sl1 = 0.f;

    for (int kt = 0; kt < 32; kt++) {
        CP_WAIT0();
        __syncthreads();
        if (kt < 31) { issue_kv(kt + 1, (kt + 1) & 1); CP_COMMIT(); }

        const unsigned sb = smb + (AST_OFF + (kt & 1) * AST_STR) * 4;
        const unsigned kh = sb + kfb;
        const unsigned kl = kh + 4352 * 4;
        const unsigned vh = sb + 8704 * 4 + vfb;
        const unsigned vl = vh + 4352 * 4;

        // ---- scores: 16 q x 64 keys ----
        float sc[8][4];
#pragma unroll
        for (int nt = 0; nt < 8; nt++)
#pragma unroll
            for (int i = 0; i < 4; i++) sc[nt][i] = 0.f;

#pragma unroll
        for (int ks = 0; ks < 8; ks++) {
            unsigned ah[4], al[4];
            ldsm_x4(ah, qah + ks * 32);
            ldsm_x4(al, qal + ks * 32);
#pragma unroll
            for (int n2 = 0; n2 < 4; n2++) {
                unsigned bh4[4], bl4[4];
                unsigned off = n2 * (16 * 68 * 4) + ks * 32;
                ldsm_x4(bh4, kh + off);
                ldsm_x4(bl4, kl + off);
                mma_bf16(sc[2 * n2],     ah, bh4,     sc[2 * n2]);
                mma_bf16(sc[2 * n2],     ah, bl4,     sc[2 * n2]);
                mma_bf16(sc[2 * n2],     al, bh4,     sc[2 * n2]);
                mma_bf16(sc[2 * n2 + 1], ah, bh4 + 2, sc[2 * n2 + 1]);
                mma_bf16(sc[2 * n2 + 1], ah, bl4 + 2, sc[2 * n2 + 1]);
                mma_bf16(sc[2 * n2 + 1], al, bh4 + 2, sc[2 * n2 + 1]);
            }
        }

        // ---- online softmax (rows g, g+8) ----
        float t0 = -1e30f, t1 = -1e30f;
#pragma unroll
        for (int nt = 0; nt < 8; nt++) {
            t0 = fmaxf(t0, fmaxf(sc[nt][0], sc[nt][1]));
            t1 = fmaxf(t1, fmaxf(sc[nt][2], sc[nt][3]));
        }
        t0 = fmaxf(t0, __shfl_xor_sync(0xffffffffu, t0, 1));
        t0 = fmaxf(t0, __shfl_xor_sync(0xffffffffu, t0, 2));
        t1 = fmaxf(t1, __shfl_xor_sync(0xffffffffu, t1, 1));
        t1 = fmaxf(t1, __shfl_xor_sync(0xffffffffu, t1, 2));
        float mn0 = fmaxf(m0, t0), mn1 = fmaxf(m1, t1);
        float al0 = __expf(m0 - mn0), al1 = __expf(m1 - mn1);
        m0 = mn0; m1 = mn1;
        float s0 = 0.f, s1 = 0.f;
#pragma unroll
        for (int nt = 0; nt < 8; nt++) {
            sc[nt][0] = __expf(sc[nt][0] - mn0); s0 += sc[nt][0];
            sc[nt][1] = __expf(sc[nt][1] - mn0); s0 += sc[nt][1];
            sc[nt][2] = __expf(sc[nt][2] - mn1); s1 += sc[nt][2];
            sc[nt][3] = __expf(sc[nt][3] - mn1); s1 += sc[nt][3];
        }
        s0 += __shfl_xor_sync(0xffffffffu, s0, 1);
        s0 += __shfl_xor_sync(0xffffffffu, s0, 2);
        s1 += __shfl_xor_sync(0xffffffffu, s1, 1);
        s1 += __shfl_xor_sync(0xffffffffu, s1, 2);
        sl0 = sl0 * al0 + s0;
        sl1 = sl1 * al1 + s1;
#pragma unroll
        for (int nt = 0; nt < 16; nt++) {
            o_[nt][0] *= al0; o_[nt][1] *= al0;
            o_[nt][2] *= al1; o_[nt][3] *= al1;
        }

        // ---- O += P V ----
#pragma unroll
        for (int ks = 0; ks < 4; ks++) {
            unsigned ah[4], al[4];
            split_pair(sc[2 * ks][0],     sc[2 * ks][1],     ah[0], al[0]);
            split_pair(sc[2 * ks][2],     sc[2 * ks][3],     ah[1], al[1]);
            split_pair(sc[2 * ks + 1][0], sc[2 * ks + 1][1], ah[2], al[2]);
            split_pair(sc[2 * ks + 1][2], sc[2 * ks + 1][3], ah[3], al[3]);
#pragma unroll
            for (int np = 0; np < 8; np++) {
                unsigned bh4[4], bl4[4];
                unsigned off = (ks * 16 * 68 + np * 8) * 4;
                ldsm_x4t(bh4, vh + off);
                ldsm_x4t(bl4, vl + off);
                mma_bf16(o_[2 * np],     ah, bh4,     o_[2 * np]);
                mma_bf16(o_[2 * np],     ah, bl4,     o_[2 * np]);
                mma_bf16(o_[2 * np],     al, bh4,     o_[2 * np]);
                mma_bf16(o_[2 * np + 1], ah, bh4 + 2, o_[2 * np + 1]);
                mma_bf16(o_[2 * np + 1], ah, bl4 + 2, o_[2 * np + 1]);
                mma_bf16(o_[2 * np + 1], al, bh4 + 2, o_[2 * np + 1]);
            }
        }
    }

    // ---- epilogue: normalize, sigmoid-gate, write SPLIT ctx ----
    float inv0 = 1.f / sl0, inv1 = 1.f / sl1;
    int qrow0 = q0 + warp * 16 + g;
    int qrow1 = qrow0 + 8;
    const float* g0p = g_gate + ((size_t)((b * S_LEN + qrow0) * NH + hh)) * HD;
    const float* g1p = g_gate + ((size_t)((b * S_LEN + qrow1) * NH + hh)) * HD;
    size_t cw0 = (size_t)(b * S_LEN + qrow0) * 512 + hh * 64;
    size_t cw1 = (size_t)(b * S_LEN + qrow1) * 512 + hh * 64;
#pragma unroll
    for (int nt = 0; nt < 16; nt++) {
        int d = nt * 8 + 2 * c;
        float2 gA = *(const float2*)(g0p + d);
        float oAx = o_[nt][0] * inv0 * (1.f / (1.f + __expf(-gA.x)));
        float oAy = o_[nt][1] * inv0 * (1.f / (1.f + __expf(-gA.y)));
        unsigned uh, ul;
        split_pair(oAx, oAy, uh, ul);
        g_ctxh[cw0 + nt * 4 + c] = uh;
        g_ctxl[cw0 + nt * 4 + c] = ul;
        float2 gB = *(const float2*)(g1p + d);
        float oBx = o_[nt][2] * inv1 * (1.f / (1.f + __expf(-gB.x)));
        float oBy = o_[nt][3] * inv1 * (1.f / (1.f + __expf(-gB.y)));
        split_pair(oBx, oBy, uh, ul);
        g_ctxh[cw1 + nt * 4 + c] = uh;
        g_ctxl[cw1 + nt * 4 + c] = ul;
    }
}

// -----------------------------------------------------------------------------
extern "C" void kernel_launch(void* const* d_in, const int* in_sizes, int n_in,
                              void* d_out, int out_size)
{
    const float* hidden = (const float*)d_in[0];
    const float* rope   = (const float*)d_in[1];
    const float* Wq     = (const float*)d_in[2];
    const float* bq     = (const float*)d_in[3];
    const float* Wk     = (const float*)d_in[4];
    const float* bk     = (const float*)d_in[5];
    const float* Wv     = (const float*)d_in[6];
    const float* bv     = (const float*)d_in[7];
    const float* Wo     = (const float*)d_in[8];
    const float* bo     = (const float*)d_in[9];
    const float* qw     = (const float*)d_in[10];
    const float* kw     = (const float*)d_in[11];
    float* out = (float*)d_out;

    unsigned *hidh, *hidl, *wqkvh, *wqkvl, *woh, *wol, *ctxh, *ctxl;
    float *qkv, *biasq;
    cudaGetSymbolAddress((void**)&hidh,  g_hidh);
    cudaGetSymbolAddress((void**)&hidl,  g_hidl);
    cudaGetSymbolAddress((void**)&wqkvh, g_wqkvh);
    cudaGetSymbolAddress((void**)&wqkvl, g_wqkvl);
    cudaGetSymbolAddress((void**)&woh,   g_woh);
    cudaGetSymbolAddress((void**)&wol,   g_wol);
    cudaGetSymbolAddress((void**)&ctxh,  g_ctxh);
    cudaGetSymbolAddress((void**)&ctxl,  g_ctxl);
    cudaGetSymbolAddress((void**)&qkv,   g_qkv);
    cudaGetSymbolAddress((void**)&biasq, g_biasqkv);

    cudaFuncSetAttribute((const void*)gemm_bf16s,
                         cudaFuncAttributeMaxDynamicSharedMemorySize, GEMM_SMEM_BYTES);
    cudaFuncSetAttribute((const void*)attn_kernel,
                         cudaFuncAttributeMaxDynamicSharedMemorySize, ATT_SMEM_BYTES);

    // one-shot splits
    split2d<<<8192, 256>>>(hidden, hidh,  hidl,  256, 512,  0);
    split2d<<<2048, 256>>>(Wq,     wqkvh, wqkvl, 512, 1280, 0);
    split2d<<<256,  256>>>(Wk,     wqkvh, wqkvl, 64,  1280, 1024);
    split2d<<<256,  256>>>(Wv,     wqkvh, wqkvl, 64,  1280, 1152);
    split2d<<<1024, 256>>>(Wo,     woh,   wol,   256, 512,  0);
    concat_bias<<<10, 256>>>(bq, bk, bv);

    // fused QKV projection
    gemm_bf16s<<<dim3(20, 64), 256, GEMM_SMEM_BYTES>>>(
        hidh, hidl, wqkvh, wqkvl, biasq, qkv, 1280, 2560);

    transform_kernel<<<M_ROWS, 384>>>(qkv, rope, qw, kw);

    attn_kernel<<<dim3(16, NH, NB), 256, ATT_SMEM_BYTES>>>();

    gemm_bf16s<<<dim3(8, 64), 256, GEMM_SMEM_BYTES>>>(
        ctxh, ctxl, woh, wol, bo, out, 512, 1024);
}